// round 11
// baseline (speedup 1.0000x reference)
#include <cuda_runtime.h>
#include <cuda_bf16.h>
#include <math.h>
#include <stdint.h>

#define BATCH 4
#define SEQ   2048
#define EMB   1024
#define NH    16
#define HS    64
#define DFF   4096
#define MROWS (BATCH*SEQ)   // 8192
#define QKVW  (3*EMB)       // 3072

// ---------------- scratch (device globals; no allocation) ----------------
__device__ __align__(256) __nv_bfloat16 g_ahi [MROWS*EMB];
__device__ __align__(256) __nv_bfloat16 g_alo [MROWS*EMB];
__device__ __align__(256) __nv_bfloat16 g_ffhi[MROWS*DFF];
__device__ __align__(256) __nv_bfloat16 g_fflo[MROWS*DFF];
__device__ __align__(256) __nv_bfloat16 g_qkvh[MROWS*QKVW];
__device__ __align__(256) __nv_bfloat16 g_qkvl[MROWS*QKVW];
__device__ __align__(256) __nv_bfloat16 g_wqkvh[QKVW*EMB];
__device__ __align__(256) __nv_bfloat16 g_wqkvl[QKVW*EMB];
__device__ __align__(256) __nv_bfloat16 g_wprojh[EMB*EMB];
__device__ __align__(256) __nv_bfloat16 g_wprojl[EMB*EMB];
__device__ __align__(256) __nv_bfloat16 g_wff1h[DFF*EMB];
__device__ __align__(256) __nv_bfloat16 g_wff1l[DFF*EMB];
__device__ __align__(256) __nv_bfloat16 g_wff2h[EMB*DFF];
__device__ __align__(256) __nv_bfloat16 g_wff2l[EMB*DFF];
__device__ __align__(256) float g_x1 [MROWS*EMB];
__device__ int g_len[BATCH];

// ---------------- helpers ----------------
__device__ __forceinline__ uint32_t smem_u32(const void* p) {
    uint32_t a;
    asm("{ .reg .u64 t; cvta.to.shared.u64 t, %1; cvt.u32.u64 %0, t; }" : "=r"(a) : "l"(p));
    return a;
}
__device__ __forceinline__ void cp_async16(uint32_t dst, const void* src) {
    asm volatile("cp.async.cg.shared.global [%0], [%1], 16;\n" :: "r"(dst), "l"(src));
}
#define CP_COMMIT() asm volatile("cp.async.commit_group;\n" ::: "memory")
#define CP_WAIT0()  asm volatile("cp.async.wait_group 0;\n" ::: "memory")
#define CP_WAIT1()  asm volatile("cp.async.wait_group 1;\n" ::: "memory")

__device__ __forceinline__ void ldsm4(uint32_t* r, uint32_t addr) {
    asm volatile("ldmatrix.sync.aligned.m8n8.x4.shared.b16 {%0,%1,%2,%3}, [%4];"
        : "=r"(r[0]), "=r"(r[1]), "=r"(r[2]), "=r"(r[3]) : "r"(addr));
}
__device__ __forceinline__ void ldsm4t(uint32_t* r, uint32_t addr) {
    asm volatile("ldmatrix.sync.aligned.m8n8.x4.trans.shared.b16 {%0,%1,%2,%3}, [%4];"
        : "=r"(r[0]), "=r"(r[1]), "=r"(r[2]), "=r"(r[3]) : "r"(addr));
}
__device__ __forceinline__ void mma_bf16(float* d, const uint32_t* a, const uint32_t* b) {
    asm volatile("mma.sync.aligned.m16n8k16.row.col.f32.bf16.bf16.f32 "
        "{%0,%1,%2,%3}, {%4,%5,%6,%7}, {%8,%9}, {%0,%1,%2,%3};"
        : "+f"(d[0]), "+f"(d[1]), "+f"(d[2]), "+f"(d[3])
        : "r"(a[0]), "r"(a[1]), "r"(a[2]), "r"(a[3]), "r"(b[0]), "r"(b[1]));
}
__device__ __forceinline__ uint32_t sw128(uint32_t off) {
    return off ^ ((off >> 3) & 0x70);
}
__device__ __forceinline__ void split_bf16(float v, __nv_bfloat16& h, __nv_bfloat16& l) {
    h = __float2bfloat16(v);
    l = __float2bfloat16(v - __bfloat162float(h));
}
// split pair (a,b) into packed hi bf16x2 and lo bf16x2 (a in low half)
__device__ __forceinline__ void split2(float a, float b, uint32_t& hi, uint32_t& lo) {
    __nv_bfloat16 ha = __float2bfloat16(a), hb = __float2bfloat16(b);
    __nv_bfloat162 hh; hh.x = ha; hh.y = hb;
    hi = *(uint32_t*)&hh;
    __nv_bfloat162 ll;
    ll.x = __float2bfloat16(a - __bfloat162float(ha));
    ll.y = __float2bfloat16(b - __bfloat162float(hb));
    lo = *(uint32_t*)&ll;
}

// ---------------- lengths from key_padding_mask (dtype-robust) ----------------
__global__ void lengths_kernel(const unsigned char* mraw) {
    __shared__ int s_cnt[BATCH];
    __shared__ int s_isbool;
    int tid = threadIdx.x;
    if (tid < BATCH) s_cnt[tid] = 0;
    if (tid == 0) s_isbool = (mraw[1] | mraw[2] | mraw[3]) ? 1 : 0;
    __syncthreads();
    for (int b = 0; b < BATCH; b++) {
        int c = 0;
        if (s_isbool) {
            const unsigned char* p = mraw + (size_t)b * SEQ;
            for (int t = tid; t < SEQ; t += blockDim.x) c += p[t] ? 1 : 0;
        } else {
            const int* p = (const int*)mraw + (size_t)b * SEQ;
            for (int t = tid; t < SEQ; t += blockDim.x) c += p[t] ? 1 : 0;
        }
        atomicAdd(&s_cnt[b], c);
    }
    __syncthreads();
    if (tid < BATCH) g_len[tid] = s_cnt[tid];
}

// ---------------- weight transpose + hi/lo split: W[K,N] -> T[N,K] bf16 x2 ----------------
__global__ void __launch_bounds__(256) wsplit_kernel(
    const float* __restrict__ W, __nv_bfloat16* __restrict__ Th,
    __nv_bfloat16* __restrict__ Tl, int K, int N, int rowOff, int ldt)
{
    __shared__ float t[32][33];
    int n0 = blockIdx.x * 32, k0 = blockIdx.y * 32;
    int tx = threadIdx.x & 31, ty = threadIdx.x >> 5;
    #pragma unroll
    for (int i = 0; i < 32; i += 8)
        t[ty + i][tx] = W[(size_t)(k0 + ty + i) * N + n0 + tx];
    __syncthreads();
    #pragma unroll
    for (int i = 0; i < 32; i += 8) {
        float v = t[tx][ty + i];
        size_t o = (size_t)(rowOff + n0 + ty + i) * ldt + k0 + tx;
        __nv_bfloat16 h, l; split_bf16(v, h, l);
        Th[o] = h; Tl[o] = l;
    }
}

// ---------------- LayerNorm -> masked, bf16 hi/lo split output ----------------
__global__ void __launch_bounds__(256) ln_split_kernel(
    const float* __restrict__ x, const float* __restrict__ w,
    const float* __restrict__ bia, __nv_bfloat16* __restrict__ yh,
    __nv_bfloat16* __restrict__ yl)
{
    int row = blockIdx.x;
    int b = row >> 11, t = row & (SEQ - 1);
    const float* xr = x + (size_t)row * EMB;
    float s = 0.f, sq = 0.f;
    for (int i = threadIdx.x; i < EMB; i += 256) { float v = xr[i]; s += v; sq += v * v; }
    #pragma unroll
    for (int o = 16; o; o >>= 1) {
        s  += __shfl_xor_sync(~0u, s,  o);
        sq += __shfl_xor_sync(~0u, sq, o);
    }
    __shared__ float red[16];
    __shared__ float s_mu, s_rstd;
    int wid = threadIdx.x >> 5, lid = threadIdx.x & 31;
    if (lid == 0) { red[wid] = s; red[8 + wid] = sq; }
    __syncthreads();
    if (threadIdx.x == 0) {
        float S = 0.f, SQ = 0.f;
        for (int i = 0; i < 8; i++) { S += red[i]; SQ += red[8 + i]; }
        float mu = S * (1.f / EMB);
        float var = SQ * (1.f / EMB) - mu * mu;
        s_mu = mu; s_rstd = rsqrtf(var + 1e-5f);
    }
    __syncthreads();
    float mk = (t < g_len[b]) ? 1.f : 0.f;
    float mu = s_mu, rstd = s_rstd;
    for (int i = threadIdx.x; i < EMB; i += 256) {
        float v = ((xr[i] - mu) * rstd * w[i] + bia[i]) * mk;
        __nv_bfloat16 h, l; split_bf16(v, h, l);
        yh[(size_t)row * EMB + i] = h;
        yl[(size_t)row * EMB + i] = l;
    }
}

// ---------------- mma.sync GEMM, K-chunk 32, hi|lo interleaved rows ----------------
// C[M,N] = A @ B^T (split-bf16, fp32 acc). 128x128 tile, 8 warps (2x4).
// Stage = A-tile 16KB + B-tile 16KB (row = [hi 64B | lo 64B]); 3 stages = 96KB
// -> 2 CTAs/SM. __launch_bounds__(256,2) keeps regs <= 128.
#define GEMM_SMEM (3 * 32768)

__global__ void __launch_bounds__(256, 2) gemm_mma(
    const __nv_bfloat16* __restrict__ Ahi, const __nv_bfloat16* __restrict__ Alo,
    const __nv_bfloat16* __restrict__ Bhi, const __nv_bfloat16* __restrict__ Blo,
    const float* __restrict__ Res, const float* __restrict__ Bias,
    float* __restrict__ Cf, __nv_bfloat16* __restrict__ Chi, __nv_bfloat16* __restrict__ Clo,
    int K, int ldc, int doRelu, int doMask)
{
    extern __shared__ char smem[];
    uint32_t sb = smem_u32(smem);
    int tid = threadIdx.x;
    int lane = tid & 31, wid = tid >> 5;
    int wm = (wid >> 2) * 64;
    int wn = (wid & 3) * 32;
    int m0 = blockIdx.y * 128, n0 = blockIdx.x * 128;

    int nc = K >> 5;   // chunks of 32 columns

    // stage layout: [A-tile 16KB][B-tile 16KB]; row r = 128B: units 0-3 hi, 4-7 lo
    auto load_chunk = [&](uint32_t st, int kc) {
        #pragma unroll
        for (int i = 0; i < 8; i++) {
            int g = tid + i * 256;          // 0..2047
            int tile = g >> 10;             // 0 = A, 1 = B
            int rem = g & 1023;
            int r = rem >> 3, u = rem & 7;
            uint32_t sw = sw128(r * 128 + u * 16);
            int col = kc + (u & 3) * 8;
            const __nv_bfloat16* src;
            if (tile == 0)
                src = ((u < 4) ? Ahi : Alo) + (size_t)(m0 + r) * K + col;
            else
                src = ((u < 4) ? Bhi : Blo) + (size_t)(n0 + r) * K + col;
            cp_async16(st + tile * 16384 + sw, src);
        }
        CP_COMMIT();
    };

    int grp = lane >> 3, lrow = lane & 7;
    int a_r = lrow + ((grp & 1) ? 8 : 0);
    int a_c = grp >> 1;
    int b_r = lrow + ((grp >> 1) ? 8 : 0);
    int b_c = grp & 1;

    float d[4][4][4];
    #pragma unroll
    for (int i = 0; i < 4; i++)
        #pragma unroll
        for (int j = 0; j < 4; j++)
            #pragma unroll
            for (int q = 0; q < 4; q++) d[i][j][q] = 0.f;

    load_chunk(sb, 0);
    load_chunk(sb + 32768, 32);
    CP_WAIT1();
    __syncthreads();

    for (int c = 0; c < nc; c++) {
        uint32_t st = sb + (c % 3) * 32768;
        if (c + 2 < nc) load_chunk(sb + ((c + 2) % 3) * 32768, (c + 2) * 32);

        #pragma unroll
        for (int ks = 0; ks < 2; ks++) {
            uint32_t ah[4][4], al[4][4];
            #pragma unroll
            for (int mt = 0; mt < 4; mt++) {
                uint32_t rb = (wm + mt * 16 + a_r) * 128;
                ldsm4(ah[mt], st + sw128(rb + (2 * ks + a_c) * 16));
                ldsm4(al[mt], st + sw128(rb + (4 + 2 * ks + a_c) * 16));
            }
            #pragma unroll
            for (int np = 0; np < 2; np++) {
                uint32_t rb = (wn + np * 16 + b_r) * 128;
                uint32_t th[4], tl[4];
                ldsm4(th, st + 16384 + sw128(rb + (2 * ks + b_c) * 16));
                ldsm4(tl, st + 16384 + sw128(rb + (4 + 2 * ks + b_c) * 16));
                #pragma unroll
                for (int mt = 0; mt < 4; mt++) {
                    mma_bf16(d[mt][np * 2],     ah[mt], &th[0]);
                    mma_bf16(d[mt][np * 2],     ah[mt], &tl[0]);
                    mma_bf16(d[mt][np * 2],     al[mt], &th[0]);
                    mma_bf16(d[mt][np * 2 + 1], ah[mt], &th[2]);
                    mma_bf16(d[mt][np * 2 + 1], ah[mt], &tl[2]);
                    mma_bf16(d[mt][np * 2 + 1], al[mt], &th[2]);
                }
            }
        }
        if (c + 2 < nc) CP_WAIT1(); else CP_WAIT0();
        __syncthreads();
    }

    // ---- epilogue: stage f32 accum through smem (reuse stage memory) ----
    float* eb = (float*)smem;    // [128][132]
    int fr = lane >> 2, fc = (lane & 3) * 2;
    #pragma unroll
    for (int mt = 0; mt < 4; mt++)
        #pragma unroll
        for (int nt = 0; nt < 4; nt++) {
            int rr = wm + mt * 16 + fr;
            int cc = wn + nt * 8 + fc;
            *(float2*)&eb[rr * 132 + cc]       = make_float2(d[mt][nt][0], d[mt][nt][1]);
            *(float2*)&eb[(rr + 8) * 132 + cc] = make_float2(d[mt][nt][2], d[mt][nt][3]);
        }
    __syncthreads();

    #pragma unroll
    for (int it = 0; it < 16; it++) {
        int idx = tid + it * 256;
        int rr = idx >> 5;
        int cc = (idx & 31) * 4;
        int m = m0 + rr, n = n0 + cc;
        float4 v = *(float4*)&eb[rr * 132 + cc];
        if (Bias) {
            v.x += Bias[n]; v.y += Bias[n + 1]; v.z += Bias[n + 2]; v.w += Bias[n + 3];
        }
        if (Res) {
            float4 rv = *(const float4*)&Res[(size_t)m * ldc + n];
            v.x += rv.x; v.y += rv.y; v.z += rv.z; v.w += rv.w;
        }
        if (doRelu) {
            v.x = fmaxf(v.x, 0.f); v.y = fmaxf(v.y, 0.f);
            v.z = fmaxf(v.z, 0.f); v.w = fmaxf(v.w, 0.f);
        }
        if (doMask) {
            int bb = m >> 11, t = m & (SEQ - 1);
            float mk = (t < g_len[bb]) ? 1.f : 0.f;
            v.x *= mk; v.y *= mk; v.z *= mk; v.w *= mk;
        }
        if (Chi) {
            __nv_bfloat16 h[4], l[4];
            split_bf16(v.x, h[0], l[0]); split_bf16(v.y, h[1], l[1]);
            split_bf16(v.z, h[2], l[2]); split_bf16(v.w, h[3], l[3]);
            *(uint2*)&Chi[(size_t)m * ldc + n] = *(uint2*)h;
            *(uint2*)&Clo[(size_t)m * ldc + n] = *(uint2*)l;
        } else {
            *(float4*)&Cf[(size_t)m * ldc + n] = v;
        }
    }
}

// ---------------- Flash attention with split-bf16 mma.sync ----------------
// 128q x 64k tiles, 8 warps (16 q-rows each), softmax in registers.
// K/V tiles loaded once per 128 queries (half the traffic of 64q CTAs).
#define ATTN_SMEM 65536

__global__ void __launch_bounds__(256) attn_mma_kernel(
    const __nv_bfloat16* __restrict__ QKVh, const __nv_bfloat16* __restrict__ QKVl,
    __nv_bfloat16* __restrict__ Oh, __nv_bfloat16* __restrict__ Ol)
{
    extern __shared__ char smem[];
    uint32_t sb = smem_u32(smem);
    const uint32_t sQh = sb,          sQl = sb + 16384,
                   sKh = sb + 32768,  sKl = sb + 40960,
                   sVh = sb + 49152,  sVl = sb + 57344;
    int tid = threadIdx.x, lane = tid & 31, wid = tid >> 5;
    int b = blockIdx.z, h = blockIdx.y, qt = blockIdx.x;
    int q0 = qt * 128;
    int len = g_len[b];
    size_t rowbase = (size_t)b * SEQ;
    int cq = h * HS, ck = EMB + h * HS, cv = 2 * EMB + h * HS;

    // load Q tile 128 rows (hi/lo), SW128
    #pragma unroll
    for (int i = 0; i < 4; i++) {
        int idx = tid + i * 256;           // 0..1023
        int r = idx >> 3, c16 = idx & 7;
        uint32_t sw = sw128(r * 128 + c16 * 16);
        size_t g = (rowbase + q0 + r) * QKVW + cq + c16 * 8;
        cp_async16(sQh + sw, QKVh + g);
        cp_async16(sQl + sw, QKVl + g);
    }
    CP_COMMIT();

    float Oacc[8][4];
    #pragma unroll
    for (int j = 0; j < 8; j++)
        #pragma unroll
        for (int q = 0; q < 4; q++) Oacc[j][q] = 0.f;
    float mrow0 = -1e30f, mrow1 = -1e30f, lrow0 = 0.f, lrow1 = 0.f;

    const float scale = 0.03125f;  // 1024^-0.5
    int lenTiles = (len + 63) >> 6;
    int nT = min(2 * qt + 2, lenTiles);

    int l15 = lane & 15, lh = lane >> 4;
    int grp = lane >> 3, lrow = lane & 7;
    int b_r = lrow + ((grp >> 1) ? 8 : 0);   // B-operand lane addressing (as in gemm)
    int b_c = grp & 1;
    int wq = wid * 16;                       // warp q-row offset, 0..112
    int r0 = q0 + wq + (lane >> 2);          // global seq row of d0,d1 (row+8 for d2,d3)
    int dlo = (lane & 3) * 2;

    for (int kt = 0; kt < nT; kt++) {
        int s0 = kt * 64;
        __syncthreads();   // all warps done reading previous K/V
        #pragma unroll
        for (int i = 0; i < 2; i++) {
            int idx = tid + i * 256;       // 0..511
            int r = idx >> 3, c16 = idx & 7;
            uint32_t sw = sw128(r * 128 + c16 * 16);
            size_t gk = (rowbase + s0 + r) * QKVW + ck + c16 * 8;
            size_t gv = (rowbase + s0 + r) * QKVW + cv + c16 * 8;
            cp_async16(sKh + sw, QKVh + gk);
            cp_async16(sKl + sw, QKVl + gk);
            cp_async16(sVh + sw, QKVh + gv);
            cp_async16(sVl + sw, QKVl + gv);
        }
        CP_COMMIT();
        CP_WAIT0();
        __syncthreads();

        // ---- S = Q K^T (3-term split), fp32 frags ----
        float sacc[8][4];
        #pragma unroll
        for (int j = 0; j < 8; j++)
            #pragma unroll
            for (int q = 0; q < 4; q++) sacc[j][q] = 0.f;

        #pragma unroll
        for (int ks = 0; ks < 4; ks++) {
            uint32_t qh[4], ql[4];
            uint32_t aoff = sw128((wq + l15) * 128 + (ks * 2 + lh) * 16);
            ldsm4(qh, sQh + aoff);
            ldsm4(ql, sQl + aoff);
            #pragma unroll
            for (int np = 0; np < 4; np++) {
                uint32_t boff = sw128((np * 16 + b_r) * 128 + (ks * 2 + b_c) * 16);
                uint32_t kh[4], kl[4];
                ldsm4(kh, sKh + boff);
                ldsm4(kl, sKl + boff);
                mma_bf16(sacc[np * 2],     qh, &kh[0]);
                mma_bf16(sacc[np * 2],     qh, &kl[0]);
                mma_bf16(sacc[np * 2],     ql, &kh[0]);
                mma_bf16(sacc[np * 2 + 1], qh, &kh[2]);
                mma_bf16(sacc[np * 2 + 1], qh, &kl[2]);
                mma_bf16(sacc[np * 2 + 1], ql, &kh[2]);
            }
        }

        // ---- scale + mask + row max ----
        float rmax0 = -1e30f, rmax1 = -1e30f;
        #pragma unroll
        for (int j = 0; j < 8; j++) {
            int kj = s0 + j * 8 + dlo;
            #pragma unroll
            for (int q = 0; q < 4; q++) {
                int col = kj + (q & 1);
                int row = r0 + (q >> 1) * 8;
                float v = sacc[j][q] * scale;
                if (col > row || col >= len) v = -1e30f;
                sacc[j][q] = v;
            }
            rmax0 = fmaxf(rmax0, fmaxf(sacc[j][0], sacc[j][1]));
            rmax1 = fmaxf(rmax1, fmaxf(sacc[j][2], sacc[j][3]));
        }
        rmax0 = fmaxf(rmax0, __shfl_xor_sync(~0u, rmax0, 1));
        rmax0 = fmaxf(rmax0, __shfl_xor_sync(~0u, rmax0, 2));
        rmax1 = fmaxf(rmax1, __shfl_xor_sync(~0u, rmax1, 1));
        rmax1 = fmaxf(rmax1, __shfl_xor_sync(~0u, rmax1, 2));

        float mnew0 = fmaxf(mrow0, rmax0), mnew1 = fmaxf(mrow1, rmax1);
        float corr0 = __expf(mrow0 - mnew0), corr1 = __expf(mrow1 - mnew1);
        mrow0 = mnew0; mrow1 = mnew1;

        // ---- P = exp(S - m), row sums ----
        float rsum0 = 0.f, rsum1 = 0.f;
        #pragma unroll
        for (int j = 0; j < 8; j++) {
            sacc[j][0] = __expf(sacc[j][0] - mnew0);
            sacc[j][1] = __expf(sacc[j][1] - mnew0);
            sacc[j][2] = __expf(sacc[j][2] - mnew1);
            sacc[j][3] = __expf(sacc[j][3] - mnew1);
            rsum0 += sacc[j][0] + sacc[j][1];
            rsum1 += sacc[j][2] + sacc[j][3];
        }
        rsum0 += __shfl_xor_sync(~0u, rsum0, 1);
        rsum0 += __shfl_xor_sync(~0u, rsum0, 2);
        rsum1 += __shfl_xor_sync(~0u, rsum1, 1);
        rsum1 += __shfl_xor_sync(~0u, rsum1, 2);
        lrow0 = lrow0 * corr0 + rsum0;
        lrow1 = lrow1 * corr1 + rsum1;

        // ---- rescale O ----
        #pragma unroll
        for (int j = 0; j < 8; j++) {
            Oacc[j][0] *= corr0; Oacc[j][1] *= corr0;
            Oacc[j][2] *= corr1; Oacc[j][3] *= corr1;
        }

        // ---- O += P @ V (3-term split), V via ldmatrix.trans ----
        #pragma unroll
        for (int ks = 0; ks < 4; ks++) {
            int j0 = 2 * ks, j1 = j0 + 1;
            uint32_t ph[4], pl[4];
            split2(sacc[j0][0], sacc[j0][1], ph[0], pl[0]);
            split2(sacc[j0][2], sacc[j0][3], ph[1], pl[1]);
            split2(sacc[j1][0], sacc[j1][1], ph[2], pl[2]);
            split2(sacc[j1][2], sacc[j1][3], ph[3], pl[3]);
            #pragma unroll
            for (int dg = 0; dg < 4; dg++) {
                uint32_t voff = sw128((ks * 16 + l15) * 128 + (dg * 2 + lh) * 16);
                uint32_t vh[4], vl[4];
                ldsm4t(vh, sVh + voff);
                ldsm4t(vl, sVl + voff);
                mma_bf16(Oacc[dg * 2],     ph, &vh[0]);
                mma_bf16(Oacc[dg * 2],     ph, &vl[0]);
                mma_bf16(Oacc[dg * 2],     pl, &vh[0]);
                mma_bf16(Oacc[dg * 2 + 1], ph, &vh[2]);
                mma_bf16(Oacc[dg * 2 + 1], ph, &vl[2]);
                mma_bf16(Oacc[dg * 2 + 1], pl, &vh[2]);
            }
        }
    }

    // ---- final: O /= l, write bf16 hi/lo ----
    float inv0 = 1.f / lrow0, inv1 = 1.f / lrow1;
    size_t row0 = rowbase + r0, row1 = row0 + 8;
    #pragma unroll
    for (int j = 0; j < 8; j++) {
        int dc = h * HS + j * 8 + dlo;
        uint32_t uh, ul;
        split2(Oacc[j][0] * inv0, Oacc[j][1] * inv0, uh, ul);
        *(uint32_t*)&Oh[row0 * EMB + dc] = uh;
        *(uint32_t*)&Ol[row0 * EMB + dc] = ul;
        split2(Oacc[j][2] * inv1, Oacc[j][3] * inv1, uh, ul);
        *(uint32_t*)&Oh[row1 * EMB + dc] = uh;
        *(uint32_t*)&Ol[row1 * EMB + dc] = ul;
    }
}

// ---------------- launch ----------------
extern "C" void kernel_launch(void* const* d_in, const int* in_sizes, int n_in,
                              void* d_out, int out_size)
{
    const float* x      = (const float*)d_in[0];
    const unsigned char* mask = (const unsigned char*)d_in[1];
    const float* wq     = (const float*)d_in[2];
    const float* wk     = (const float*)d_in[3];
    const float* wv     = (const float*)d_in[4];
    const float* proj_w = (const float*)d_in[5];
    const float* proj_b = (const float*)d_in[6];
    const float* ff_w1  = (const float*)d_in[7];
    const float* ff_b1  = (const float*)d_in[8];
    const float* ff_w2  = (const float*)d_in[9];
    const float* ff_b2  = (const float*)d_in[10];
    const float* ln1w   = (const float*)d_in[11];
    const float* ln1b   = (const float*)d_in[12];
    const float* ln2w   = (const float*)d_in[13];
    const float* ln2b   = (const float*)d_in[14];
    float* out = (float*)d_out;

    __nv_bfloat16 *ahi, *alo, *ffh, *ffl, *qkvh, *qkvl;
    __nv_bfloat16 *wqkvh, *wqkvl, *wprojh, *wprojl, *wff1h, *wff1l, *wff2h, *wff2l;
    float *x1;
    cudaGetSymbolAddress((void**)&ahi, g_ahi);   cudaGetSymbolAddress((void**)&alo, g_alo);
    cudaGetSymbolAddress((void**)&ffh, g_ffhi);  cudaGetSymbolAddress((void**)&ffl, g_fflo);
    cudaGetSymbolAddress((void**)&qkvh, g_qkvh); cudaGetSymbolAddress((void**)&qkvl, g_qkvl);
    cudaGetSymbolAddress((void**)&wqkvh, g_wqkvh); cudaGetSymbolAddress((void**)&wqkvl, g_wqkvl);
    cudaGetSymbolAddress((void**)&wprojh, g_wprojh); cudaGetSymbolAddress((void**)&wprojl, g_wprojl);
    cudaGetSymbolAddress((void**)&wff1h, g_wff1h); cudaGetSymbolAddress((void**)&wff1l, g_wff1l);
    cudaGetSymbolAddress((void**)&wff2h, g_wff2h); cudaGetSymbolAddress((void**)&wff2l, g_wff2l);
    cudaGetSymbolAddress((void**)&x1, g_x1);

    cudaFuncSetAttribute(gemm_mma, cudaFuncAttributeMaxDynamicSharedMemorySize, GEMM_SMEM);
    cudaFuncSetAttribute(attn_mma_kernel, cudaFuncAttributeMaxDynamicSharedMemorySize, ATTN_SMEM);

    // Launch order arranged so launch #6 (ncu -s 5 -c 1) is the QKV GEMM.
    lengths_kernel<<<1, 256>>>(mask);                                          // 1
    wsplit_kernel<<<dim3(EMB/32, EMB/32), 256>>>(wq, wqkvh, wqkvl, EMB, EMB, 0,     EMB);  // 2
    wsplit_kernel<<<dim3(EMB/32, EMB/32), 256>>>(wk, wqkvh, wqkvl, EMB, EMB, EMB,   EMB);  // 3
    wsplit_kernel<<<dim3(EMB/32, EMB/32), 256>>>(wv, wqkvh, wqkvl, EMB, EMB, 2*EMB, EMB);  // 4
    ln_split_kernel<<<MROWS, 256>>>(x, ln1w, ln1b, ahi, alo);                  // 5

    // 6: qkv = h @ Wqkv^T -> bf16 hi/lo  [8192 x 3072]  (ncu capture target)
    gemm_mma<<<dim3(QKVW/128, MROWS/128), 256, GEMM_SMEM>>>(
        ahi, alo, wqkvh, wqkvl, nullptr, nullptr, nullptr, qkvh, qkvl,
        EMB, QKVW, 0, 0);

    // attention (tensor-core flash, 128 q-rows/CTA) -> ahi/alo
    attn_mma_kernel<<<dim3(SEQ/128, NH, BATCH), 256, ATTN_SMEM>>>(qkvh, qkvl, ahi, alo);

    wsplit_kernel<<<dim3(EMB/32, EMB/32), 256>>>(proj_w, wprojh, wprojl, EMB, EMB, 0, EMB);

    // x1 = x + attn @ proj_w + proj_b
    gemm_mma<<<dim3(EMB/128, MROWS/128), 256, GEMM_SMEM>>>(
        ahi, alo, wprojh, wprojl, x, proj_b, x1, nullptr, nullptr,
        EMB, EMB, 0, 0);

    // h2 = LN2(x1)*m (split)
    ln_split_kernel<<<MROWS, 256>>>(x1, ln2w, ln2b, ahi, alo);

    wsplit_kernel<<<dim3(DFF/32, EMB/32), 256>>>(ff_w1, wff1h, wff1l, EMB, DFF, 0, EMB);

    // ff = relu(h2 @ ff_w1 + b1) -> bf16 hi/lo
    gemm_mma<<<dim3(DFF/128, MROWS/128), 256, GEMM_SMEM>>>(
        ahi, alo, wff1h, wff1l, nullptr, ff_b1, nullptr, ffh, ffl,
        EMB, DFF, 1, 0);

    wsplit_kernel<<<dim3(EMB/32, DFF/32), 256>>>(ff_w2, wff2h, wff2l, DFF, EMB, 0, DFF);

    // out = (x1 + ff @ ff_w2 + b2) * m
    gemm_mma<<<dim3(EMB/128, MROWS/128), 256, GEMM_SMEM>>>(
        ffh, ffl, wff2h, wff2l, x1, ff_b2, out, nullptr, nullptr,
        DFF, EMB, 0, 1);
}

// round 12
// speedup vs baseline: 1.6021x; 1.6021x over previous
#include <cuda_runtime.h>
#include <cuda_bf16.h>
#include <cuda_fp16.h>
#include <math.h>
#include <stdint.h>

#define BATCH 4
#define SEQ   2048
#define EMB   1024
#define NH    16
#define HS    64
#define DFF   4096
#define MROWS (BATCH*SEQ)   // 8192
#define QKVW  (3*EMB)       // 3072

// ---------------- scratch (device globals; no allocation) ----------------
__device__ __align__(256) __nv_bfloat16 g_ahi [MROWS*EMB];   // also reused as __half h2
__device__ __align__(256) __nv_bfloat16 g_alo [MROWS*EMB];
__device__ __align__(256) __half        g_ffh [MROWS*DFF];   // ff intermediate (fp16)
__device__ __align__(256) __nv_bfloat16 g_qkvh[MROWS*QKVW];
__device__ __align__(256) __nv_bfloat16 g_qkvl[MROWS*QKVW];
__device__ __align__(256) __nv_bfloat16 g_wqkvh[QKVW*EMB];
__device__ __align__(256) __nv_bfloat16 g_wqkvl[QKVW*EMB];
__device__ __align__(256) __nv_bfloat16 g_wprojh[EMB*EMB];
__device__ __align__(256) __nv_bfloat16 g_wprojl[EMB*EMB];
__device__ __align__(256) __half        g_wff1[DFF*EMB];
__device__ __align__(256) __half        g_wff2[EMB*DFF];
__device__ __align__(256) float g_x1 [MROWS*EMB];
__device__ int g_len[BATCH];

// ---------------- helpers ----------------
__device__ __forceinline__ uint32_t smem_u32(const void* p) {
    uint32_t a;
    asm("{ .reg .u64 t; cvta.to.shared.u64 t, %1; cvt.u32.u64 %0, t; }" : "=r"(a) : "l"(p));
    return a;
}
__device__ __forceinline__ void cp_async16(uint32_t dst, const void* src) {
    asm volatile("cp.async.cg.shared.global [%0], [%1], 16;\n" :: "r"(dst), "l"(src));
}
#define CP_COMMIT() asm volatile("cp.async.commit_group;\n" ::: "memory")
#define CP_WAIT0()  asm volatile("cp.async.wait_group 0;\n" ::: "memory")
#define CP_WAIT1()  asm volatile("cp.async.wait_group 1;\n" ::: "memory")

__device__ __forceinline__ void ldsm4(uint32_t* r, uint32_t addr) {
    asm volatile("ldmatrix.sync.aligned.m8n8.x4.shared.b16 {%0,%1,%2,%3}, [%4];"
        : "=r"(r[0]), "=r"(r[1]), "=r"(r[2]), "=r"(r[3]) : "r"(addr));
}
__device__ __forceinline__ void ldsm4t(uint32_t* r, uint32_t addr) {
    asm volatile("ldmatrix.sync.aligned.m8n8.x4.trans.shared.b16 {%0,%1,%2,%3}, [%4];"
        : "=r"(r[0]), "=r"(r[1]), "=r"(r[2]), "=r"(r[3]) : "r"(addr));
}
__device__ __forceinline__ void mma_bf16(float* d, const uint32_t* a, const uint32_t* b) {
    asm volatile("mma.sync.aligned.m16n8k16.row.col.f32.bf16.bf16.f32 "
        "{%0,%1,%2,%3}, {%4,%5,%6,%7}, {%8,%9}, {%0,%1,%2,%3};"
        : "+f"(d[0]), "+f"(d[1]), "+f"(d[2]), "+f"(d[3])
        : "r"(a[0]), "r"(a[1]), "r"(a[2]), "r"(a[3]), "r"(b[0]), "r"(b[1]));
}
__device__ __forceinline__ void mma_f16(float* d, const uint32_t* a, const uint32_t* b) {
    asm volatile("mma.sync.aligned.m16n8k16.row.col.f32.f16.f16.f32 "
        "{%0,%1,%2,%3}, {%4,%5,%6,%7}, {%8,%9}, {%0,%1,%2,%3};"
        : "+f"(d[0]), "+f"(d[1]), "+f"(d[2]), "+f"(d[3])
        : "r"(a[0]), "r"(a[1]), "r"(a[2]), "r"(a[3]), "r"(b[0]), "r"(b[1]));
}
__device__ __forceinline__ uint32_t sw128(uint32_t off) {
    return off ^ ((off >> 3) & 0x70);
}
__device__ __forceinline__ void split_bf16(float v, __nv_bfloat16& h, __nv_bfloat16& l) {
    h = __float2bfloat16(v);
    l = __float2bfloat16(v - __bfloat162float(h));
}
__device__ __forceinline__ void split2(float a, float b, uint32_t& hi, uint32_t& lo) {
    __nv_bfloat16 ha = __float2bfloat16(a), hb = __float2bfloat16(b);
    __nv_bfloat162 hh; hh.x = ha; hh.y = hb;
    hi = *(uint32_t*)&hh;
    __nv_bfloat162 ll;
    ll.x = __float2bfloat16(a - __bfloat162float(ha));
    ll.y = __float2bfloat16(b - __bfloat162float(hb));
    lo = *(uint32_t*)&ll;
}

// ---------------- lengths from key_padding_mask (dtype-robust) ----------------
__global__ void lengths_kernel(const unsigned char* mraw) {
    __shared__ int s_cnt[BATCH];
    __shared__ int s_isbool;
    int tid = threadIdx.x;
    if (tid < BATCH) s_cnt[tid] = 0;
    if (tid == 0) s_isbool = (mraw[1] | mraw[2] | mraw[3]) ? 1 : 0;
    __syncthreads();
    for (int b = 0; b < BATCH; b++) {
        int c = 0;
        if (s_isbool) {
            const unsigned char* p = mraw + (size_t)b * SEQ;
            for (int t = tid; t < SEQ; t += blockDim.x) c += p[t] ? 1 : 0;
        } else {
            const int* p = (const int*)mraw + (size_t)b * SEQ;
            for (int t = tid; t < SEQ; t += blockDim.x) c += p[t] ? 1 : 0;
        }
        atomicAdd(&s_cnt[b], c);
    }
    __syncthreads();
    if (tid < BATCH) g_len[tid] = s_cnt[tid];
}

// ---------------- weight transpose + hi/lo split: W[K,N] -> T[N,K] bf16 x2 ----------------
__global__ void __launch_bounds__(256) wsplit_kernel(
    const float* __restrict__ W, __nv_bfloat16* __restrict__ Th,
    __nv_bfloat16* __restrict__ Tl, int K, int N, int rowOff, int ldt)
{
    __shared__ float t[32][33];
    int n0 = blockIdx.x * 32, k0 = blockIdx.y * 32;
    int tx = threadIdx.x & 31, ty = threadIdx.x >> 5;
    #pragma unroll
    for (int i = 0; i < 32; i += 8)
        t[ty + i][tx] = W[(size_t)(k0 + ty + i) * N + n0 + tx];
    __syncthreads();
    #pragma unroll
    for (int i = 0; i < 32; i += 8) {
        float v = t[tx][ty + i];
        size_t o = (size_t)(rowOff + n0 + ty + i) * ldt + k0 + tx;
        __nv_bfloat16 h, l; split_bf16(v, h, l);
        Th[o] = h; Tl[o] = l;
    }
}

// ---------------- weight transpose -> fp16 single: W[K,N] -> T[N,K] ----------------
__global__ void __launch_bounds__(256) wsplit_h_kernel(
    const float* __restrict__ W, __half* __restrict__ T, int K, int N, int ldt)
{
    __shared__ float t[32][33];
    int n0 = blockIdx.x * 32, k0 = blockIdx.y * 32;
    int tx = threadIdx.x & 31, ty = threadIdx.x >> 5;
    #pragma unroll
    for (int i = 0; i < 32; i += 8)
        t[ty + i][tx] = W[(size_t)(k0 + ty + i) * N + n0 + tx];
    __syncthreads();
    #pragma unroll
    for (int i = 0; i < 32; i += 8)
        T[(size_t)(n0 + ty + i) * ldt + k0 + tx] = __float2half(t[tx][ty + i]);
}

// ---------------- LayerNorm -> masked, bf16 hi/lo split output ----------------
__global__ void __launch_bounds__(256) ln_split_kernel(
    const float* __restrict__ x, const float* __restrict__ w,
    const float* __restrict__ bia, __nv_bfloat16* __restrict__ yh,
    __nv_bfloat16* __restrict__ yl)
{
    int row = blockIdx.x;
    int b = row >> 11, t = row & (SEQ - 1);
    const float* xr = x + (size_t)row * EMB;
    float s = 0.f, sq = 0.f;
    for (int i = threadIdx.x; i < EMB; i += 256) { float v = xr[i]; s += v; sq += v * v; }
    #pragma unroll
    for (int o = 16; o; o >>= 1) {
        s  += __shfl_xor_sync(~0u, s,  o);
        sq += __shfl_xor_sync(~0u, sq, o);
    }
    __shared__ float red[16];
    __shared__ float s_mu, s_rstd;
    int wid = threadIdx.x >> 5, lid = threadIdx.x & 31;
    if (lid == 0) { red[wid] = s; red[8 + wid] = sq; }
    __syncthreads();
    if (threadIdx.x == 0) {
        float S = 0.f, SQ = 0.f;
        for (int i = 0; i < 8; i++) { S += red[i]; SQ += red[8 + i]; }
        float mu = S * (1.f / EMB);
        float var = SQ * (1.f / EMB) - mu * mu;
        s_mu = mu; s_rstd = rsqrtf(var + 1e-5f);
    }
    __syncthreads();
    float mk = (t < g_len[b]) ? 1.f : 0.f;
    float mu = s_mu, rstd = s_rstd;
    for (int i = threadIdx.x; i < EMB; i += 256) {
        float v = ((xr[i] - mu) * rstd * w[i] + bia[i]) * mk;
        __nv_bfloat16 h, l; split_bf16(v, h, l);
        yh[(size_t)row * EMB + i] = h;
        yl[(size_t)row * EMB + i] = l;
    }
}

// ---------------- LayerNorm -> masked, fp16 single output ----------------
__global__ void __launch_bounds__(256) ln_half_kernel(
    const float* __restrict__ x, const float* __restrict__ w,
    const float* __restrict__ bia, __half* __restrict__ y)
{
    int row = blockIdx.x;
    int b = row >> 11, t = row & (SEQ - 1);
    const float* xr = x + (size_t)row * EMB;
    float s = 0.f, sq = 0.f;
    for (int i = threadIdx.x; i < EMB; i += 256) { float v = xr[i]; s += v; sq += v * v; }
    #pragma unroll
    for (int o = 16; o; o >>= 1) {
        s  += __shfl_xor_sync(~0u, s,  o);
        sq += __shfl_xor_sync(~0u, sq, o);
    }
    __shared__ float red[16];
    __shared__ float s_mu, s_rstd;
    int wid = threadIdx.x >> 5, lid = threadIdx.x & 31;
    if (lid == 0) { red[wid] = s; red[8 + wid] = sq; }
    __syncthreads();
    if (threadIdx.x == 0) {
        float S = 0.f, SQ = 0.f;
        for (int i = 0; i < 8; i++) { S += red[i]; SQ += red[8 + i]; }
        float mu = S * (1.f / EMB);
        float var = SQ * (1.f / EMB) - mu * mu;
        s_mu = mu; s_rstd = rsqrtf(var + 1e-5f);
    }
    __syncthreads();
    float mk = (t < g_len[b]) ? 1.f : 0.f;
    float mu = s_mu, rstd = s_rstd;
    for (int i = threadIdx.x; i < EMB; i += 256)
        y[(size_t)row * EMB + i] = __float2half(((xr[i] - mu) * rstd * w[i] + bia[i]) * mk);
}

// ---------------- split-bf16 GEMM (3-term), K-chunk 32, hi|lo interleaved ----------------
#define GEMM_SMEM (3 * 32768)

__global__ void __launch_bounds__(256, 2) gemm_mma(
    const __nv_bfloat16* __restrict__ Ahi, const __nv_bfloat16* __restrict__ Alo,
    const __nv_bfloat16* __restrict__ Bhi, const __nv_bfloat16* __restrict__ Blo,
    const float* __restrict__ Res, const float* __restrict__ Bias,
    float* __restrict__ Cf, __nv_bfloat16* __restrict__ Chi, __nv_bfloat16* __restrict__ Clo,
    int K, int ldc, int doRelu, int doMask)
{
    extern __shared__ char smem[];
    uint32_t sb = smem_u32(smem);
    int tid = threadIdx.x;
    int lane = tid & 31, wid = tid >> 5;
    int wm = (wid >> 2) * 64;
    int wn = (wid & 3) * 32;
    int m0 = blockIdx.y * 128, n0 = blockIdx.x * 128;

    int nc = K >> 5;

    auto load_chunk = [&](uint32_t st, int kc) {
        #pragma unroll
        for (int i = 0; i < 8; i++) {
            int g = tid + i * 256;
            int tile = g >> 10;
            int rem = g & 1023;
            int r = rem >> 3, u = rem & 7;
            uint32_t sw = sw128(r * 128 + u * 16);
            int col = kc + (u & 3) * 8;
            const __nv_bfloat16* src;
            if (tile == 0)
                src = ((u < 4) ? Ahi : Alo) + (size_t)(m0 + r) * K + col;
            else
                src = ((u < 4) ? Bhi : Blo) + (size_t)(n0 + r) * K + col;
            cp_async16(st + tile * 16384 + sw, src);
        }
        CP_COMMIT();
    };

    int grp = lane >> 3, lrow = lane & 7;
    int a_r = lrow + ((grp & 1) ? 8 : 0);
    int a_c = grp >> 1;
    int b_r = lrow + ((grp >> 1) ? 8 : 0);
    int b_c = grp & 1;

    float d[4][4][4];
    #pragma unroll
    for (int i = 0; i < 4; i++)
        #pragma unroll
        for (int j = 0; j < 4; j++)
            #pragma unroll
            for (int q = 0; q < 4; q++) d[i][j][q] = 0.f;

    load_chunk(sb, 0);
    load_chunk(sb + 32768, 32);
    CP_WAIT1();
    __syncthreads();

    for (int c = 0; c < nc; c++) {
        uint32_t st = sb + (c % 3) * 32768;
        if (c + 2 < nc) load_chunk(sb + ((c + 2) % 3) * 32768, (c + 2) * 32);

        #pragma unroll
        for (int ks = 0; ks < 2; ks++) {
            uint32_t ah[4][4], al[4][4];
            #pragma unroll
            for (int mt = 0; mt < 4; mt++) {
                uint32_t rb = (wm + mt * 16 + a_r) * 128;
                ldsm4(ah[mt], st + sw128(rb + (2 * ks + a_c) * 16));
                ldsm4(al[mt], st + sw128(rb + (4 + 2 * ks + a_c) * 16));
            }
            #pragma unroll
            for (int np = 0; np < 2; np++) {
                uint32_t rb = (wn + np * 16 + b_r) * 128;
                uint32_t th[4], tl[4];
                ldsm4(th, st + 16384 + sw128(rb + (2 * ks + b_c) * 16));
                ldsm4(tl, st + 16384 + sw128(rb + (4 + 2 * ks + b_c) * 16));
                #pragma unroll
                for (int mt = 0; mt < 4; mt++) {
                    mma_bf16(d[mt][np * 2],     ah[mt], &th[0]);
                    mma_bf16(d[mt][np * 2],     ah[mt], &tl[0]);
                    mma_bf16(d[mt][np * 2],     al[mt], &th[0]);
                    mma_bf16(d[mt][np * 2 + 1], ah[mt], &th[2]);
                    mma_bf16(d[mt][np * 2 + 1], ah[mt], &tl[2]);
                    mma_bf16(d[mt][np * 2 + 1], al[mt], &th[2]);
                }
            }
        }
        if (c + 2 < nc) CP_WAIT1(); else CP_WAIT0();
        __syncthreads();
    }

    // ---- epilogue ----
    float* eb = (float*)smem;    // [128][132]
    int fr = lane >> 2, fc = (lane & 3) * 2;
    #pragma unroll
    for (int mt = 0; mt < 4; mt++)
        #pragma unroll
        for (int nt = 0; nt < 4; nt++) {
            int rr = wm + mt * 16 + fr;
            int cc = wn + nt * 8 + fc;
            *(float2*)&eb[rr * 132 + cc]       = make_float2(d[mt][nt][0], d[mt][nt][1]);
            *(float2*)&eb[(rr + 8) * 132 + cc] = make_float2(d[mt][nt][2], d[mt][nt][3]);
        }
    __syncthreads();

    #pragma unroll
    for (int it = 0; it < 16; it++) {
        int idx = tid + it * 256;
        int rr = idx >> 5;
        int cc = (idx & 31) * 4;
        int m = m0 + rr, n = n0 + cc;
        float4 v = *(float4*)&eb[rr * 132 + cc];
        if (Bias) {
            v.x += Bias[n]; v.y += Bias[n + 1]; v.z += Bias[n + 2]; v.w += Bias[n + 3];
        }
        if (Res) {
            float4 rv = *(const float4*)&Res[(size_t)m * ldc + n];
            v.x += rv.x; v.y += rv.y; v.z += rv.z; v.w += rv.w;
        }
        if (doRelu) {
            v.x = fmaxf(v.x, 0.f); v.y = fmaxf(v.y, 0.f);
            v.z = fmaxf(v.z, 0.f); v.w = fmaxf(v.w, 0.f);
        }
        if (doMask) {
            int bb = m >> 11, t = m & (SEQ - 1);
            float mk = (t < g_len[bb]) ? 1.f : 0.f;
            v.x *= mk; v.y *= mk; v.z *= mk; v.w *= mk;
        }
        if (Chi) {
            __nv_bfloat16 h[4], l[4];
            split_bf16(v.x, h[0], l[0]); split_bf16(v.y, h[1], l[1]);
            split_bf16(v.z, h[2], l[2]); split_bf16(v.w, h[3], l[3]);
            *(uint2*)&Chi[(size_t)m * ldc + n] = *(uint2*)h;
            *(uint2*)&Clo[(size_t)m * ldc + n] = *(uint2*)l;
        } else {
            *(float4*)&Cf[(size_t)m * ldc + n] = v;
        }
    }
}

// ---------------- single-term fp16 GEMM, K-chunk 64 ----------------
// C[M,N] = A @ B^T, A half [M,K], B half [N,K]. Same tiling: 128x128, 8 warps.
__global__ void __launch_bounds__(256, 2) gemm_fp16(
    const __half* __restrict__ A, const __half* __restrict__ B,
    const float* __restrict__ Res, const float* __restrict__ Bias,
    float* __restrict__ Cf, __half* __restrict__ Ch,
    int K, int ldc, int doRelu, int doMask)
{
    extern __shared__ char smem[];
    uint32_t sb = smem_u32(smem);
    int tid = threadIdx.x;
    int lane = tid & 31, wid = tid >> 5;
    int wm = (wid >> 2) * 64;
    int wn = (wid & 3) * 32;
    int m0 = blockIdx.y * 128, n0 = blockIdx.x * 128;

    int nc = K >> 6;   // chunks of 64 columns (128B rows of half)

    auto load_chunk = [&](uint32_t st, int kc) {
        #pragma unroll
        for (int i = 0; i < 8; i++) {
            int g = tid + i * 256;          // 0..2047
            int tile = g >> 10;             // 0 = A, 1 = B
            int rem = g & 1023;
            int r = rem >> 3, u = rem & 7;
            uint32_t sw = sw128(r * 128 + u * 16);
            int col = kc + u * 8;
            const __half* src = (tile == 0) ? A + (size_t)(m0 + r) * K + col
                                            : B + (size_t)(n0 + r) * K + col;
            cp_async16(st + tile * 16384 + sw, src);
        }
        CP_COMMIT();
    };

    int grp = lane >> 3, lrow = lane & 7;
    int a_r = lrow + ((grp & 1) ? 8 : 0);
    int a_c = grp >> 1;
    int b_r = lrow + ((grp >> 1) ? 8 : 0);
    int b_c = grp & 1;

    float d[4][4][4];
    #pragma unroll
    for (int i = 0; i < 4; i++)
        #pragma unroll
        for (int j = 0; j < 4; j++)
            #pragma unroll
            for (int q = 0; q < 4; q++) d[i][j][q] = 0.f;

    load_chunk(sb, 0);
    load_chunk(sb + 32768, 64);
    CP_WAIT1();
    __syncthreads();

    for (int c = 0; c < nc; c++) {
        uint32_t st = sb + (c % 3) * 32768;
        if (c + 2 < nc) load_chunk(sb + ((c + 2) % 3) * 32768, (c + 2) * 64);

        #pragma unroll
        for (int ks = 0; ks < 4; ks++) {
            uint32_t ah[4][4];
            #pragma unroll
            for (int mt = 0; mt < 4; mt++) {
                uint32_t rb = (wm + mt * 16 + a_r) * 128;
                ldsm4(ah[mt], st + sw128(rb + (2 * ks + a_c) * 16));
            }
            #pragma unroll
            for (int np = 0; np < 2; np++) {
                uint32_t rb = (wn + np * 16 + b_r) * 128;
                uint32_t th[4];
                ldsm4(th, st + 16384 + sw128(rb + (2 * ks + b_c) * 16));
                #pragma unroll
                for (int mt = 0; mt < 4; mt++) {
                    mma_f16(d[mt][np * 2],     ah[mt], &th[0]);
                    mma_f16(d[mt][np * 2 + 1], ah[mt], &th[2]);
                }
            }
        }
        if (c + 2 < nc) CP_WAIT1(); else CP_WAIT0();
        __syncthreads();
    }

    // ---- epilogue ----
    float* eb = (float*)smem;    // [128][132]
    int fr = lane >> 2, fc = (lane & 3) * 2;
    #pragma unroll
    for (int mt = 0; mt < 4; mt++)
        #pragma unroll
        for (int nt = 0; nt < 4; nt++) {
            int rr = wm + mt * 16 + fr;
            int cc = wn + nt * 8 + fc;
            *(float2*)&eb[rr * 132 + cc]       = make_float2(d[mt][nt][0], d[mt][nt][1]);
            *(float2*)&eb[(rr + 8) * 132 + cc] = make_float2(d[mt][nt][2], d[mt][nt][3]);
        }
    __syncthreads();

    #pragma unroll
    for (int it = 0; it < 16; it++) {
        int idx = tid + it * 256;
        int rr = idx >> 5;
        int cc = (idx & 31) * 4;
        int m = m0 + rr, n = n0 + cc;
        float4 v = *(float4*)&eb[rr * 132 + cc];
        if (Bias) {
            v.x += Bias[n]; v.y += Bias[n + 1]; v.z += Bias[n + 2]; v.w += Bias[n + 3];
        }
        if (Res) {
            float4 rv = *(const float4*)&Res[(size_t)m * ldc + n];
            v.x += rv.x; v.y += rv.y; v.z += rv.z; v.w += rv.w;
        }
        if (doRelu) {
            v.x = fmaxf(v.x, 0.f); v.y = fmaxf(v.y, 0.f);
            v.z = fmaxf(v.z, 0.f); v.w = fmaxf(v.w, 0.f);
        }
        if (doMask) {
            int bb = m >> 11, t = m & (SEQ - 1);
            float mk = (t < g_len[bb]) ? 1.f : 0.f;
            v.x *= mk; v.y *= mk; v.z *= mk; v.w *= mk;
        }
        if (Ch) {
            __half h[4];
            h[0] = __float2half(v.x); h[1] = __float2half(v.y);
            h[2] = __float2half(v.z); h[3] = __float2half(v.w);
            *(uint2*)&Ch[(size_t)m * ldc + n] = *(uint2*)h;
        } else {
            *(float4*)&Cf[(size_t)m * ldc + n] = v;
        }
    }
}

// ---------------- Flash attention with split-bf16 mma.sync (64q, 4 warps) ----------------
#define ATTN_SMEM (6 * 8192)

__global__ void __launch_bounds__(128) attn_mma_kernel(
    const __nv_bfloat16* __restrict__ QKVh, const __nv_bfloat16* __restrict__ QKVl,
    __nv_bfloat16* __restrict__ Oh, __nv_bfloat16* __restrict__ Ol)
{
    extern __shared__ char smem[];
    uint32_t sb = smem_u32(smem);
    const uint32_t sQh = sb, sQl = sb + 8192, sKh = sb + 16384, sKl = sb + 24576,
                   sVh = sb + 32768, sVl = sb + 40960;
    int tid = threadIdx.x, lane = tid & 31, wid = tid >> 5;
    int b = blockIdx.z, h = blockIdx.y, qt = blockIdx.x;
    int q0 = qt * 64;
    int len = g_len[b];
    size_t rowbase = (size_t)b * SEQ;
    int cq = h * HS, ck = EMB + h * HS, cv = 2 * EMB + h * HS;

    #pragma unroll
    for (int i = 0; i < 4; i++) {
        int idx = tid + i * 128;
        int r = idx >> 3, c16 = idx & 7;
        uint32_t sw = sw128(r * 128 + c16 * 16);
        size_t g = (rowbase + q0 + r) * QKVW + cq + c16 * 8;
        cp_async16(sQh + sw, QKVh + g);
        cp_async16(sQl + sw, QKVl + g);
    }
    CP_COMMIT();

    float Oacc[8][4];
    #pragma unroll
    for (int j = 0; j < 8; j++)
        #pragma unroll
        for (int q = 0; q < 4; q++) Oacc[j][q] = 0.f;
    float mrow0 = -1e30f, mrow1 = -1e30f, lrow0 = 0.f, lrow1 = 0.f;

    const float scale = 0.03125f;  // 1024^-0.5
    int lenTiles = (len + 63) >> 6;
    int nT = min(qt + 1, lenTiles);

    int l15 = lane & 15, lh = lane >> 4;
    int grp = lane >> 3, lrow = lane & 7;
    int b_r = lrow + ((grp >> 1) ? 8 : 0);
    int b_c = grp & 1;
    int wq = wid * 16;
    int r0 = q0 + wq + (lane >> 2);
    int dlo = (lane & 3) * 2;

    for (int kt = 0; kt < nT; kt++) {
        int s0 = kt * 64;
        __syncthreads();
        #pragma unroll
        for (int i = 0; i < 4; i++) {
            int idx = tid + i * 128;
            int r = idx >> 3, c16 = idx & 7;
            uint32_t sw = sw128(r * 128 + c16 * 16);
            size_t gk = (rowbase + s0 + r) * QKVW + ck + c16 * 8;
            size_t gv = (rowbase + s0 + r) * QKVW + cv + c16 * 8;
            cp_async16(sKh + sw, QKVh + gk);
            cp_async16(sKl + sw, QKVl + gk);
            cp_async16(sVh + sw, QKVh + gv);
            cp_async16(sVl + sw, QKVl + gv);
        }
        CP_COMMIT();
        CP_WAIT0();
        __syncthreads();

        float sacc[8][4];
        #pragma unroll
        for (int j = 0; j < 8; j++)
            #pragma unroll
            for (int q = 0; q < 4; q++) sacc[j][q] = 0.f;

        #pragma unroll
        for (int ks = 0; ks < 4; ks++) {
            uint32_t qh[4], ql[4];
            uint32_t aoff = sw128((wq + l15) * 128 + (ks * 2 + lh) * 16);
            ldsm4(qh, sQh + aoff);
            ldsm4(ql, sQl + aoff);
            #pragma unroll
            for (int np = 0; np < 4; np++) {
                uint32_t boff = sw128((np * 16 + b_r) * 128 + (ks * 2 + b_c) * 16);
                uint32_t kh[4], kl[4];
                ldsm4(kh, sKh + boff);
                ldsm4(kl, sKl + boff);
                mma_bf16(sacc[np * 2],     qh, &kh[0]);
                mma_bf16(sacc[np * 2],     qh, &kl[0]);
                mma_bf16(sacc[np * 2],     ql, &kh[0]);
                mma_bf16(sacc[np * 2 + 1], qh, &kh[2]);
                mma_bf16(sacc[np * 2 + 1], qh, &kl[2]);
                mma_bf16(sacc[np * 2 + 1], ql, &kh[2]);
            }
        }

        float rmax0 = -1e30f, rmax1 = -1e30f;
        #pragma unroll
        for (int j = 0; j < 8; j++) {
            int kj = s0 + j * 8 + dlo;
            #pragma unroll
            for (int q = 0; q < 4; q++) {
                int col = kj + (q & 1);
                int row = r0 + (q >> 1) * 8;
                float v = sacc[j][q] * scale;
                if (col > row || col >= len) v = -1e30f;
                sacc[j][q] = v;
            }
            rmax0 = fmaxf(rmax0, fmaxf(sacc[j][0], sacc[j][1]));
            rmax1 = fmaxf(rmax1, fmaxf(sacc[j][2], sacc[j][3]));
        }
        rmax0 = fmaxf(rmax0, __shfl_xor_sync(~0u, rmax0, 1));
        rmax0 = fmaxf(rmax0, __shfl_xor_sync(~0u, rmax0, 2));
        rmax1 = fmaxf(rmax1, __shfl_xor_sync(~0u, rmax1, 1));
        rmax1 = fmaxf(rmax1, __shfl_xor_sync(~0u, rmax1, 2));

        float mnew0 = fmaxf(mrow0, rmax0), mnew1 = fmaxf(mrow1, rmax1);
        float corr0 = __expf(mrow0 - mnew0), corr1 = __expf(mrow1 - mnew1);
        mrow0 = mnew0; mrow1 = mnew1;

        float rsum0 = 0.f, rsum1 = 0.f;
        #pragma unroll
        for (int j = 0; j < 8; j++) {
            sacc[j][0] = __expf(sacc[j][0] - mnew0);
            sacc[j][1] = __expf(sacc[j][1] - mnew0);
            sacc[j][2] = __expf(sacc[j][2] - mnew1);
            sacc[j][3] = __expf(sacc[j][3] - mnew1);
            rsum0 += sacc[j][0] + sacc[j][1];
            rsum1 += sacc[j][2] + sacc[j][3];
        }
        rsum0 += __shfl_xor_sync(~0u, rsum0, 1);
        rsum0 += __shfl_xor_sync(~0u, rsum0, 2);
        rsum1 += __shfl_xor_sync(~0u, rsum1, 1);
        rsum1 += __shfl_xor_sync(~0u, rsum1, 2);
        lrow0 = lrow0 * corr0 + rsum0;
        lrow1 = lrow1 * corr1 + rsum1;

        #pragma unroll
        for (int j = 0; j < 8; j++) {
            Oacc[j][0] *= corr0; Oacc[j][1] *= corr0;
            Oacc[j][2] *= corr1; Oacc[j][3] *= corr1;
        }

        #pragma unroll
        for (int ks = 0; ks < 4; ks++) {
            int j0 = 2 * ks, j1 = j0 + 1;
            uint32_t ph[4], pl[4];
            split2(sacc[j0][0], sacc[j0][1], ph[0], pl[0]);
            split2(sacc[j0][2], sacc[j0][3], ph[1], pl[1]);
            split2(sacc[j1][0], sacc[j1][1], ph[2], pl[2]);
            split2(sacc[j1][2], sacc[j1][3], ph[3], pl[3]);
            #pragma unroll
            for (int dg = 0; dg < 4; dg++) {
                uint32_t voff = sw128((ks * 16 + l15) * 128 + (dg * 2 + lh) * 16);
                uint32_t vh[4], vl[4];
                ldsm4t(vh, sVh + voff);
                ldsm4t(vl, sVl + voff);
                mma_bf16(Oacc[dg * 2],     ph, &vh[0]);
                mma_bf16(Oacc[dg * 2],     ph, &vl[0]);
                mma_bf16(Oacc[dg * 2],     pl, &vh[0]);
                mma_bf16(Oacc[dg * 2 + 1], ph, &vh[2]);
                mma_bf16(Oacc[dg * 2 + 1], ph, &vl[2]);
                mma_bf16(Oacc[dg * 2 + 1], pl, &vh[2]);
            }
        }
    }

    float inv0 = 1.f / lrow0, inv1 = 1.f / lrow1;
    size_t row0 = rowbase + r0, row1 = row0 + 8;
    #pragma unroll
    for (int j = 0; j < 8; j++) {
        int dc = h * HS + j * 8 + dlo;
        uint32_t uh, ul;
        split2(Oacc[j][0] * inv0, Oacc[j][1] * inv0, uh, ul);
        *(uint32_t*)&Oh[row0 * EMB + dc] = uh;
        *(uint32_t*)&Ol[row0 * EMB + dc] = ul;
        split2(Oacc[j][2] * inv1, Oacc[j][3] * inv1, uh, ul);
        *(uint32_t*)&Oh[row1 * EMB + dc] = uh;
        *(uint32_t*)&Ol[row1 * EMB + dc] = ul;
    }
}

// ---------------- launch ----------------
extern "C" void kernel_launch(void* const* d_in, const int* in_sizes, int n_in,
                              void* d_out, int out_size)
{
    const float* x      = (const float*)d_in[0];
    const unsigned char* mask = (const unsigned char*)d_in[1];
    const float* wq     = (const float*)d_in[2];
    const float* wk     = (const float*)d_in[3];
    const float* wv     = (const float*)d_in[4];
    const float* proj_w = (const float*)d_in[5];
    const float* proj_b = (const float*)d_in[6];
    const float* ff_w1  = (const float*)d_in[7];
    const float* ff_b1  = (const float*)d_in[8];
    const float* ff_w2  = (const float*)d_in[9];
    const float* ff_b2  = (const float*)d_in[10];
    const float* ln1w   = (const float*)d_in[11];
    const float* ln1b   = (const float*)d_in[12];
    const float* ln2w   = (const float*)d_in[13];
    const float* ln2b   = (const float*)d_in[14];
    float* out = (float*)d_out;

    __nv_bfloat16 *ahi, *alo, *qkvh, *qkvl;
    __nv_bfloat16 *wqkvh, *wqkvl, *wprojh, *wprojl;
    __half *ffh, *wff1, *wff2;
    float *x1;
    cudaGetSymbolAddress((void**)&ahi, g_ahi);   cudaGetSymbolAddress((void**)&alo, g_alo);
    cudaGetSymbolAddress((void**)&ffh, g_ffh);
    cudaGetSymbolAddress((void**)&qkvh, g_qkvh); cudaGetSymbolAddress((void**)&qkvl, g_qkvl);
    cudaGetSymbolAddress((void**)&wqkvh, g_wqkvh); cudaGetSymbolAddress((void**)&wqkvl, g_wqkvl);
    cudaGetSymbolAddress((void**)&wprojh, g_wprojh); cudaGetSymbolAddress((void**)&wprojl, g_wprojl);
    cudaGetSymbolAddress((void**)&wff1, g_wff1); cudaGetSymbolAddress((void**)&wff2, g_wff2);
    cudaGetSymbolAddress((void**)&x1, g_x1);
    __half* h2 = (__half*)ahi;   // reuse (free after proj gemm)

    cudaFuncSetAttribute(gemm_mma,  cudaFuncAttributeMaxDynamicSharedMemorySize, GEMM_SMEM);
    cudaFuncSetAttribute(gemm_fp16, cudaFuncAttributeMaxDynamicSharedMemorySize, GEMM_SMEM);
    cudaFuncSetAttribute(attn_mma_kernel, cudaFuncAttributeMaxDynamicSharedMemorySize, ATTN_SMEM);

    lengths_kernel<<<1, 256>>>(mask);

    // weight prep
    wsplit_kernel<<<dim3(EMB/32, EMB/32), 256>>>(wq, wqkvh, wqkvl, EMB, EMB, 0,     EMB);
    wsplit_kernel<<<dim3(EMB/32, EMB/32), 256>>>(wk, wqkvh, wqkvl, EMB, EMB, EMB,   EMB);
    wsplit_kernel<<<dim3(EMB/32, EMB/32), 256>>>(wv, wqkvh, wqkvl, EMB, EMB, 2*EMB, EMB);
    wsplit_kernel<<<dim3(EMB/32, EMB/32), 256>>>(proj_w, wprojh, wprojl, EMB, EMB, 0, EMB);
    wsplit_h_kernel<<<dim3(DFF/32, EMB/32), 256>>>(ff_w1, wff1, EMB, DFF, EMB);
    wsplit_h_kernel<<<dim3(EMB/32, DFF/32), 256>>>(ff_w2, wff2, DFF, EMB, DFF);

    // h = LN1(x)*m (bf16 split)
    ln_split_kernel<<<MROWS, 256>>>(x, ln1w, ln1b, ahi, alo);

    // qkv = h @ Wqkv^T -> bf16 hi/lo
    gemm_mma<<<dim3(QKVW/128, MROWS/128), 256, GEMM_SMEM>>>(
        ahi, alo, wqkvh, wqkvl, nullptr, nullptr, nullptr, qkvh, qkvl,
        EMB, QKVW, 0, 0);

    // attention (64q CTAs) -> ahi/alo
    attn_mma_kernel<<<dim3(SEQ/64, NH, BATCH), 128, ATTN_SMEM>>>(qkvh, qkvl, ahi, alo);

    // x1 = x + attn @ proj_w + proj_b
    gemm_mma<<<dim3(EMB/128, MROWS/128), 256, GEMM_SMEM>>>(
        ahi, alo, wprojh, wprojl, x, proj_b, x1, nullptr, nullptr,
        EMB, EMB, 0, 0);

    // h2 = LN2(x1)*m (fp16)
    ln_half_kernel<<<MROWS, 256>>>(x1, ln2w, ln2b, h2);

    // ff = relu(h2 @ ff_w1 + b1) -> fp16
    gemm_fp16<<<dim3(DFF/128, MROWS/128), 256, GEMM_SMEM>>>(
        h2, wff1, nullptr, ff_b1, nullptr, ffh, EMB, DFF, 1, 0);

    // out = (x1 + ff @ ff_w2 + b2) * m
    gemm_fp16<<<dim3(EMB/128, MROWS/128), 256, GEMM_SMEM>>>(
        ffh, wff2, x1, ff_b2, out, nullptr, DFF, EMB, 0, 1);
}

// round 13
// speedup vs baseline: 2.5395x; 1.5851x over previous
#include <cuda_runtime.h>
#include <cuda_fp16.h>
#include <math.h>
#include <stdint.h>

#define BATCH 4
#define SEQ   2048
#define EMB   1024
#define NH    16
#define HS    64
#define DFF   4096
#define MROWS (BATCH*SEQ)   // 8192
#define QKVW  (3*EMB)       // 3072

// ---------------- scratch (device globals; no allocation) ----------------
__device__ __align__(256) __half g_h   [MROWS*EMB];    // LN out; reused for attn out
__device__ __align__(256) __half g_qkv [MROWS*QKVW];
__device__ __align__(256) __half g_ffh [MROWS*DFF];
__device__ __align__(256) __half g_wqkv[QKVW*EMB];
__device__ __align__(256) __half g_wproj[EMB*EMB];
__device__ __align__(256) __half g_wff1[DFF*EMB];
__device__ __align__(256) __half g_wff2[EMB*DFF];
__device__ __align__(256) float  g_x1  [MROWS*EMB];
__device__ int g_len[BATCH];

// ---------------- helpers ----------------
__device__ __forceinline__ uint32_t smem_u32(const void* p) {
    uint32_t a;
    asm("{ .reg .u64 t; cvta.to.shared.u64 t, %1; cvt.u32.u64 %0, t; }" : "=r"(a) : "l"(p));
    return a;
}
__device__ __forceinline__ void cp_async16(uint32_t dst, const void* src) {
    asm volatile("cp.async.cg.shared.global [%0], [%1], 16;\n" :: "r"(dst), "l"(src));
}
#define CP_COMMIT() asm volatile("cp.async.commit_group;\n" ::: "memory")
#define CP_WAIT0()  asm volatile("cp.async.wait_group 0;\n" ::: "memory")
#define CP_WAIT1()  asm volatile("cp.async.wait_group 1;\n" ::: "memory")

__device__ __forceinline__ void ldsm4(uint32_t* r, uint32_t addr) {
    asm volatile("ldmatrix.sync.aligned.m8n8.x4.shared.b16 {%0,%1,%2,%3}, [%4];"
        : "=r"(r[0]), "=r"(r[1]), "=r"(r[2]), "=r"(r[3]) : "r"(addr));
}
__device__ __forceinline__ void ldsm4t(uint32_t* r, uint32_t addr) {
    asm volatile("ldmatrix.sync.aligned.m8n8.x4.trans.shared.b16 {%0,%1,%2,%3}, [%4];"
        : "=r"(r[0]), "=r"(r[1]), "=r"(r[2]), "=r"(r[3]) : "r"(addr));
}
__device__ __forceinline__ void mma_f16(float* d, const uint32_t* a, const uint32_t* b) {
    asm volatile("mma.sync.aligned.m16n8k16.row.col.f32.f16.f16.f32 "
        "{%0,%1,%2,%3}, {%4,%5,%6,%7}, {%8,%9}, {%0,%1,%2,%3};"
        : "+f"(d[0]), "+f"(d[1]), "+f"(d[2]), "+f"(d[3])
        : "r"(a[0]), "r"(a[1]), "r"(a[2]), "r"(a[3]), "r"(b[0]), "r"(b[1]));
}
__device__ __forceinline__ uint32_t sw128(uint32_t off) {
    return off ^ ((off >> 3) & 0x70);
}
__device__ __forceinline__ uint32_t pack2h(float a, float b) {
    __half2 h = __floats2half2_rn(a, b);
    return *(uint32_t*)&h;
}

// ---------------- lengths from key_padding_mask (dtype-robust) ----------------
__global__ void lengths_kernel(const unsigned char* mraw) {
    __shared__ int s_cnt[BATCH];
    __shared__ int s_isbool;
    int tid = threadIdx.x;
    if (tid < BATCH) s_cnt[tid] = 0;
    if (tid == 0) s_isbool = (mraw[1] | mraw[2] | mraw[3]) ? 1 : 0;
    __syncthreads();
    for (int b = 0; b < BATCH; b++) {
        int c = 0;
        if (s_isbool) {
            const unsigned char* p = mraw + (size_t)b * SEQ;
            for (int t = tid; t < SEQ; t += blockDim.x) c += p[t] ? 1 : 0;
        } else {
            const int* p = (const int*)mraw + (size_t)b * SEQ;
            for (int t = tid; t < SEQ; t += blockDim.x) c += p[t] ? 1 : 0;
        }
        atomicAdd(&s_cnt[b], c);
    }
    __syncthreads();
    if (tid < BATCH) g_len[tid] = s_cnt[tid];
}

// ---------------- weight transpose -> fp16: W[K,N] -> T[N,K] ----------------
__global__ void __launch_bounds__(256) wsplit_h_kernel(
    const float* __restrict__ W, __half* __restrict__ T,
    int K, int N, int rowOff, int ldt)
{
    __shared__ float t[32][33];
    int n0 = blockIdx.x * 32, k0 = blockIdx.y * 32;
    int tx = threadIdx.x & 31, ty = threadIdx.x >> 5;
    #pragma unroll
    for (int i = 0; i < 32; i += 8)
        t[ty + i][tx] = W[(size_t)(k0 + ty + i) * N + n0 + tx];
    __syncthreads();
    #pragma unroll
    for (int i = 0; i < 32; i += 8)
        T[(size_t)(rowOff + n0 + ty + i) * ldt + k0 + tx] = __float2half(t[tx][ty + i]);
}

// ---------------- LayerNorm -> masked, fp16 output ----------------
__global__ void __launch_bounds__(256) ln_half_kernel(
    const float* __restrict__ x, const float* __restrict__ w,
    const float* __restrict__ bia, __half* __restrict__ y)
{
    int row = blockIdx.x;
    int b = row >> 11, t = row & (SEQ - 1);
    const float* xr = x + (size_t)row * EMB;
    float s = 0.f, sq = 0.f;
    for (int i = threadIdx.x; i < EMB; i += 256) { float v = xr[i]; s += v; sq += v * v; }
    #pragma unroll
    for (int o = 16; o; o >>= 1) {
        s  += __shfl_xor_sync(~0u, s,  o);
        sq += __shfl_xor_sync(~0u, sq, o);
    }
    __shared__ float red[16];
    __shared__ float s_mu, s_rstd;
    int wid = threadIdx.x >> 5, lid = threadIdx.x & 31;
    if (lid == 0) { red[wid] = s; red[8 + wid] = sq; }
    __syncthreads();
    if (threadIdx.x == 0) {
        float S = 0.f, SQ = 0.f;
        for (int i = 0; i < 8; i++) { S += red[i]; SQ += red[8 + i]; }
        float mu = S * (1.f / EMB);
        float var = SQ * (1.f / EMB) - mu * mu;
        s_mu = mu; s_rstd = rsqrtf(var + 1e-5f);
    }
    __syncthreads();
    float mk = (t < g_len[b]) ? 1.f : 0.f;
    float mu = s_mu, rstd = s_rstd;
    for (int i = threadIdx.x; i < EMB; i += 256)
        y[(size_t)row * EMB + i] = __float2half(((xr[i] - mu) * rstd * w[i] + bia[i]) * mk);
}

// ---------------- single-term fp16 GEMM, K-chunk 64, 3-stage, 2 CTAs/SM ----------------
// C[M,N] = A @ B^T, A half [M,K], B half [N,K]. 128x128 tile, 8 warps (2x4).
#define GEMM_SMEM (3 * 32768)

__global__ void __launch_bounds__(256, 2) gemm_fp16(
    const __half* __restrict__ A, const __half* __restrict__ B,
    const float* __restrict__ Res, const float* __restrict__ Bias,
    float* __restrict__ Cf, __half* __restrict__ Ch,
    int K, int ldc, int doRelu, int doMask)
{
    extern __shared__ char smem[];
    uint32_t sb = smem_u32(smem);
    int tid = threadIdx.x;
    int lane = tid & 31, wid = tid >> 5;
    int wm = (wid >> 2) * 64;
    int wn = (wid & 3) * 32;
    int m0 = blockIdx.y * 128, n0 = blockIdx.x * 128;

    int nc = K >> 6;   // chunks of 64 columns (128B rows of half)

    auto load_chunk = [&](uint32_t st, int kc) {
        #pragma unroll
        for (int i = 0; i < 8; i++) {
            int g = tid + i * 256;          // 0..2047
            int tile = g >> 10;             // 0 = A, 1 = B
            int rem = g & 1023;
            int r = rem >> 3, u = rem & 7;
            uint32_t sw = sw128(r * 128 + u * 16);
            int col = kc + u * 8;
            const __half* src = (tile == 0) ? A + (size_t)(m0 + r) * K + col
                                            : B + (size_t)(n0 + r) * K + col;
            cp_async16(st + tile * 16384 + sw, src);
        }
        CP_COMMIT();
    };

    int grp = lane >> 3, lrow = lane & 7;
    int a_r = lrow + ((grp & 1) ? 8 : 0);
    int a_c = grp >> 1;
    int b_r = lrow + ((grp >> 1) ? 8 : 0);
    int b_c = grp & 1;

    float d[4][4][4];
    #pragma unroll
    for (int i = 0; i < 4; i++)
        #pragma unroll
        for (int j = 0; j < 4; j++)
            #pragma unroll
            for (int q = 0; q < 4; q++) d[i][j][q] = 0.f;

    load_chunk(sb, 0);
    load_chunk(sb + 32768, 64);
    CP_WAIT1();
    __syncthreads();

    for (int c = 0; c < nc; c++) {
        uint32_t st = sb + (c % 3) * 32768;
        if (c + 2 < nc) load_chunk(sb + ((c + 2) % 3) * 32768, (c + 2) * 64);

        #pragma unroll
        for (int ks = 0; ks < 4; ks++) {
            uint32_t ah[4][4];
            #pragma unroll
            for (int mt = 0; mt < 4; mt++) {
                uint32_t rb = (wm + mt * 16 + a_r) * 128;
                ldsm4(ah[mt], st + sw128(rb + (2 * ks + a_c) * 16));
            }
            #pragma unroll
            for (int np = 0; np < 2; np++) {
                uint32_t rb = (wn + np * 16 + b_r) * 128;
                uint32_t th[4];
                ldsm4(th, st + 16384 + sw128(rb + (2 * ks + b_c) * 16));
                #pragma unroll
                for (int mt = 0; mt < 4; mt++) {
                    mma_f16(d[mt][np * 2],     ah[mt], &th[0]);
                    mma_f16(d[mt][np * 2 + 1], ah[mt], &th[2]);
                }
            }
        }
        if (c + 2 < nc) CP_WAIT1(); else CP_WAIT0();
        __syncthreads();
    }

    // ---- epilogue: stage f32 accum through smem ----
    float* eb = (float*)smem;    // [128][132]
    int fr = lane >> 2, fc = (lane & 3) * 2;
    #pragma unroll
    for (int mt = 0; mt < 4; mt++)
        #pragma unroll
        for (int nt = 0; nt < 4; nt++) {
            int rr = wm + mt * 16 + fr;
            int cc = wn + nt * 8 + fc;
            *(float2*)&eb[rr * 132 + cc]       = make_float2(d[mt][nt][0], d[mt][nt][1]);
            *(float2*)&eb[(rr + 8) * 132 + cc] = make_float2(d[mt][nt][2], d[mt][nt][3]);
        }
    __syncthreads();

    #pragma unroll
    for (int it = 0; it < 16; it++) {
        int idx = tid + it * 256;
        int rr = idx >> 5;
        int cc = (idx & 31) * 4;
        int m = m0 + rr, n = n0 + cc;
        float4 v = *(float4*)&eb[rr * 132 + cc];
        if (Bias) {
            v.x += Bias[n]; v.y += Bias[n + 1]; v.z += Bias[n + 2]; v.w += Bias[n + 3];
        }
        if (Res) {
            float4 rv = *(const float4*)&Res[(size_t)m * ldc + n];
            v.x += rv.x; v.y += rv.y; v.z += rv.z; v.w += rv.w;
        }
        if (doRelu) {
            v.x = fmaxf(v.x, 0.f); v.y = fmaxf(v.y, 0.f);
            v.z = fmaxf(v.z, 0.f); v.w = fmaxf(v.w, 0.f);
        }
        if (doMask) {
            int bb = m >> 11, t = m & (SEQ - 1);
            float mk = (t < g_len[bb]) ? 1.f : 0.f;
            v.x *= mk; v.y *= mk; v.z *= mk; v.w *= mk;
        }
        if (Ch) {
            uint32_t p0 = pack2h(v.x, v.y), p1 = pack2h(v.z, v.w);
            *(uint2*)&Ch[(size_t)m * ldc + n] = make_uint2(p0, p1);
        } else {
            *(float4*)&Cf[(size_t)m * ldc + n] = v;
        }
    }
}

// ---------------- Flash attention, single-term fp16 mma (64q, 4 warps) ----------------
#define ATTN_SMEM (3 * 8192)

__global__ void __launch_bounds__(128) attn_f16_kernel(
    const __half* __restrict__ QKV, __half* __restrict__ O)
{
    extern __shared__ char smem[];
    uint32_t sb = smem_u32(smem);
    const uint32_t sQ = sb, sK = sb + 8192, sV = sb + 16384;
    int tid = threadIdx.x, lane = tid & 31, wid = tid >> 5;
    int b = blockIdx.z, h = blockIdx.y, qt = blockIdx.x;
    int q0 = qt * 64;
    int len = g_len[b];
    size_t rowbase = (size_t)b * SEQ;
    int cq = h * HS, ck = EMB + h * HS, cv = 2 * EMB + h * HS;

    // load Q tile (64 rows x 128B)
    #pragma unroll
    for (int i = 0; i < 4; i++) {
        int idx = tid + i * 128;
        int r = idx >> 3, c16 = idx & 7;
        uint32_t sw = sw128(r * 128 + c16 * 16);
        cp_async16(sQ + sw, QKV + (rowbase + q0 + r) * QKVW + cq + c16 * 8);
    }
    CP_COMMIT();

    float Oacc[8][4];
    #pragma unroll
    for (int j = 0; j < 8; j++)
        #pragma unroll
        for (int q = 0; q < 4; q++) Oacc[j][q] = 0.f;
    float mrow0 = -1e30f, mrow1 = -1e30f, lrow0 = 0.f, lrow1 = 0.f;

    const float scale = 0.03125f;  // 1024^-0.5
    int lenTiles = (len + 63) >> 6;
    int nT = min(qt + 1, lenTiles);

    int l15 = lane & 15, lh = lane >> 4;
    int grp = lane >> 3, lrow = lane & 7;
    int b_r = lrow + ((grp >> 1) ? 8 : 0);   // B-operand lane addressing
    int b_c = grp & 1;
    int wq = wid * 16;
    int r0 = q0 + wq + (lane >> 2);
    int dlo = (lane & 3) * 2;

    for (int kt = 0; kt < nT; kt++) {
        int s0 = kt * 64;
        __syncthreads();
        #pragma unroll
        for (int i = 0; i < 4; i++) {
            int idx = tid + i * 128;
            int r = idx >> 3, c16 = idx & 7;
            uint32_t sw = sw128(r * 128 + c16 * 16);
            size_t gg = (rowbase + s0 + r) * QKVW + c16 * 8;
            cp_async16(sK + sw, QKV + gg + ck);
            cp_async16(sV + sw, QKV + gg + cv);
        }
        CP_COMMIT();
        CP_WAIT0();
        __syncthreads();

        // ---- S = Q K^T ----
        float sacc[8][4];
        #pragma unroll
        for (int j = 0; j < 8; j++)
            #pragma unroll
            for (int q = 0; q < 4; q++) sacc[j][q] = 0.f;

        #pragma unroll
        for (int ks = 0; ks < 4; ks++) {
            uint32_t qf[4];
            ldsm4(qf, sQ + sw128((wq + l15) * 128 + (ks * 2 + lh) * 16));
            #pragma unroll
            for (int np = 0; np < 4; np++) {
                uint32_t kf[4];
                ldsm4(kf, sK + sw128((np * 16 + b_r) * 128 + (ks * 2 + b_c) * 16));
                mma_f16(sacc[np * 2],     qf, &kf[0]);
                mma_f16(sacc[np * 2 + 1], qf, &kf[2]);
            }
        }

        // ---- scale + mask + row max ----
        float rmax0 = -1e30f, rmax1 = -1e30f;
        #pragma unroll
        for (int j = 0; j < 8; j++) {
            int kj = s0 + j * 8 + dlo;
            #pragma unroll
            for (int q = 0; q < 4; q++) {
                int col = kj + (q & 1);
                int row = r0 + (q >> 1) * 8;
                float v = sacc[j][q] * scale;
                if (col > row || col >= len) v = -1e30f;
                sacc[j][q] = v;
            }
            rmax0 = fmaxf(rmax0, fmaxf(sacc[j][0], sacc[j][1]));
            rmax1 = fmaxf(rmax1, fmaxf(sacc[j][2], sacc[j][3]));
        }
        rmax0 = fmaxf(rmax0, __shfl_xor_sync(~0u, rmax0, 1));
        rmax0 = fmaxf(rmax0, __shfl_xor_sync(~0u, rmax0, 2));
        rmax1 = fmaxf(rmax1, __shfl_xor_sync(~0u, rmax1, 1));
        rmax1 = fmaxf(rmax1, __shfl_xor_sync(~0u, rmax1, 2));

        float mnew0 = fmaxf(mrow0, rmax0), mnew1 = fmaxf(mrow1, rmax1);
        float corr0 = __expf(mrow0 - mnew0), corr1 = __expf(mrow1 - mnew1);
        mrow0 = mnew0; mrow1 = mnew1;

        // ---- P = exp(S - m), row sums ----
        float rsum0 = 0.f, rsum1 = 0.f;
        #pragma unroll
        for (int j = 0; j < 8; j++) {
            sacc[j][0] = __expf(sacc[j][0] - mnew0);
            sacc[j][1] = __expf(sacc[j][1] - mnew0);
            sacc[j][2] = __expf(sacc[j][2] - mnew1);
            sacc[j][3] = __expf(sacc[j][3] - mnew1);
            rsum0 += sacc[j][0] + sacc[j][1];
            rsum1 += sacc[j][2] + sacc[j][3];
        }
        rsum0 += __shfl_xor_sync(~0u, rsum0, 1);
        rsum0 += __shfl_xor_sync(~0u, rsum0, 2);
        rsum1 += __shfl_xor_sync(~0u, rsum1, 1);
        rsum1 += __shfl_xor_sync(~0u, rsum1, 2);
        lrow0 = lrow0 * corr0 + rsum0;
        lrow1 = lrow1 * corr1 + rsum1;

        // ---- rescale O ----
        #pragma unroll
        for (int j = 0; j < 8; j++) {
            Oacc[j][0] *= corr0; Oacc[j][1] *= corr0;
            Oacc[j][2] *= corr1; Oacc[j][3] *= corr1;
        }

        // ---- O += P @ V (P as fp16 A-fragment, V via ldmatrix.trans) ----
        #pragma unroll
        for (int ks = 0; ks < 4; ks++) {
            int j0 = 2 * ks, j1 = j0 + 1;
            uint32_t pf[4];
            pf[0] = pack2h(sacc[j0][0], sacc[j0][1]);
            pf[1] = pack2h(sacc[j0][2], sacc[j0][3]);
            pf[2] = pack2h(sacc[j1][0], sacc[j1][1]);
            pf[3] = pack2h(sacc[j1][2], sacc[j1][3]);
            #pragma unroll
            for (int dg = 0; dg < 4; dg++) {
                uint32_t vf[4];
                ldsm4t(vf, sV + sw128((ks * 16 + l15) * 128 + (dg * 2 + lh) * 16));
                mma_f16(Oacc[dg * 2],     pf, &vf[0]);
                mma_f16(Oacc[dg * 2 + 1], pf, &vf[2]);
            }
        }
    }

    // ---- final: O /= l, write fp16 ----
    float inv0 = 1.f / lrow0, inv1 = 1.f / lrow1;
    size_t row0 = rowbase + r0, row1 = row0 + 8;
    #pragma unroll
    for (int j = 0; j < 8; j++) {
        int dc = h * HS + j * 8 + dlo;
        *(uint32_t*)&O[row0 * EMB + dc] = pack2h(Oacc[j][0] * inv0, Oacc[j][1] * inv0);
        *(uint32_t*)&O[row1 * EMB + dc] = pack2h(Oacc[j][2] * inv1, Oacc[j][3] * inv1);
    }
}

// ---------------- launch ----------------
extern "C" void kernel_launch(void* const* d_in, const int* in_sizes, int n_in,
                              void* d_out, int out_size)
{
    const float* x      = (const float*)d_in[0];
    const unsigned char* mask = (const unsigned char*)d_in[1];
    const float* wq     = (const float*)d_in[2];
    const float* wk     = (const float*)d_in[3];
    const float* wv     = (const float*)d_in[4];
    const float* proj_w = (const float*)d_in[5];
    const float* proj_b = (const float*)d_in[6];
    const float* ff_w1  = (const float*)d_in[7];
    const float* ff_b1  = (const float*)d_in[8];
    const float* ff_w2  = (const float*)d_in[9];
    const float* ff_b2  = (const float*)d_in[10];
    const float* ln1w   = (const float*)d_in[11];
    const float* ln1b   = (const float*)d_in[12];
    const float* ln2w   = (const float*)d_in[13];
    const float* ln2b   = (const float*)d_in[14];
    float* out = (float*)d_out;

    __half *hbuf, *qkv, *ffh, *wqkv, *wproj, *wff1, *wff2;
    float *x1;
    cudaGetSymbolAddress((void**)&hbuf, g_h);
    cudaGetSymbolAddress((void**)&qkv, g_qkv);
    cudaGetSymbolAddress((void**)&ffh, g_ffh);
    cudaGetSymbolAddress((void**)&wqkv, g_wqkv);
    cudaGetSymbolAddress((void**)&wproj, g_wproj);
    cudaGetSymbolAddress((void**)&wff1, g_wff1);
    cudaGetSymbolAddress((void**)&wff2, g_wff2);
    cudaGetSymbolAddress((void**)&x1, g_x1);

    cudaFuncSetAttribute(gemm_fp16, cudaFuncAttributeMaxDynamicSharedMemorySize, GEMM_SMEM);
    cudaFuncSetAttribute(attn_f16_kernel, cudaFuncAttributeMaxDynamicSharedMemorySize, ATTN_SMEM);

    lengths_kernel<<<1, 256>>>(mask);

    // weight prep (transpose + fp16)
    wsplit_h_kernel<<<dim3(EMB/32, EMB/32), 256>>>(wq, wqkv, EMB, EMB, 0,     EMB);
    wsplit_h_kernel<<<dim3(EMB/32, EMB/32), 256>>>(wk, wqkv, EMB, EMB, EMB,   EMB);
    wsplit_h_kernel<<<dim3(EMB/32, EMB/32), 256>>>(wv, wqkv, EMB, EMB, 2*EMB, EMB);
    wsplit_h_kernel<<<dim3(EMB/32, EMB/32), 256>>>(proj_w, wproj, EMB, EMB, 0, EMB);
    wsplit_h_kernel<<<dim3(DFF/32, EMB/32), 256>>>(ff_w1, wff1, EMB, DFF, 0, EMB);
    wsplit_h_kernel<<<dim3(EMB/32, DFF/32), 256>>>(ff_w2, wff2, DFF, EMB, 0, DFF);

    // h = LN1(x)*m (fp16)
    ln_half_kernel<<<MROWS, 256>>>(x, ln1w, ln1b, hbuf);

    // qkv = h @ Wqkv^T -> fp16  [8192 x 3072]
    gemm_fp16<<<dim3(QKVW/128, MROWS/128), 256, GEMM_SMEM>>>(
        hbuf, wqkv, nullptr, nullptr, nullptr, qkv, EMB, QKVW, 0, 0);

    // attention (fp16 flash) -> hbuf (reuse; LN1 output no longer needed)
    attn_f16_kernel<<<dim3(SEQ/64, NH, BATCH), 128, ATTN_SMEM>>>(qkv, hbuf);

    // x1 = x + attn @ proj_w + proj_b
    gemm_fp16<<<dim3(EMB/128, MROWS/128), 256, GEMM_SMEM>>>(
        hbuf, wproj, x, proj_b, x1, nullptr, EMB, EMB, 0, 0);

    // h2 = LN2(x1)*m (fp16) -> hbuf
    ln_half_kernel<<<MROWS, 256>>>(x1, ln2w, ln2b, hbuf);

    // ff = relu(h2 @ ff_w1 + b1) -> fp16
    gemm_fp16<<<dim3(DFF/128, MROWS/128), 256, GEMM_SMEM>>>(
        hbuf, wff1, nullptr, ff_b1, nullptr, ffh, EMB, DFF, 1, 0);

    // out = (x1 + ff @ ff_w2 + b2) * m
    gemm_fp16<<<dim3(EMB/128, MROWS/128), 256, GEMM_SMEM>>>(
        ffh, wff2, x1, ff_b2, out, nullptr, DFF, EMB, 0, 1);
}

// round 17
// speedup vs baseline: 2.6820x; 1.0561x over previous
#include <cuda_runtime.h>
#include <cuda_fp16.h>
#include <math.h>
#include <stdint.h>

#define BATCH 4
#define SEQ   2048
#define EMB   1024
#define NH    16
#define HS    64
#define DFF   4096
#define MROWS (BATCH*SEQ)   // 8192
#define QKVW  (3*EMB)       // 3072

// ---------------- scratch (device globals; no allocation) ----------------
__device__ __align__(256) __half g_h   [MROWS*EMB];    // LN out; reused for attn out
__device__ __align__(256) __half g_qkv [MROWS*QKVW];
__device__ __align__(256) __half g_ffh [MROWS*DFF];
__device__ __align__(256) __half g_wqkv[QKVW*EMB];
__device__ __align__(256) __half g_wproj[EMB*EMB];
__device__ __align__(256) __half g_wff1[DFF*EMB];
__device__ __align__(256) __half g_wff2[EMB*DFF];
__device__ __align__(256) float  g_x1  [MROWS*EMB];
__device__ int g_len[BATCH];

// ---------------- helpers ----------------
__device__ __forceinline__ uint32_t smem_u32(const void* p) {
    uint32_t a;
    asm("{ .reg .u64 t; cvta.to.shared.u64 t, %1; cvt.u32.u64 %0, t; }" : "=r"(a) : "l"(p));
    return a;
}
__device__ __forceinline__ void cp_async16(uint32_t dst, const void* src) {
    asm volatile("cp.async.cg.shared.global [%0], [%1], 16;\n" :: "r"(dst), "l"(src));
}
#define CP_COMMIT() asm volatile("cp.async.commit_group;\n" ::: "memory")
#define CP_WAIT0()  asm volatile("cp.async.wait_group 0;\n" ::: "memory")
#define CP_WAIT1()  asm volatile("cp.async.wait_group 1;\n" ::: "memory")

__device__ __forceinline__ void ldsm4(uint32_t* r, uint32_t addr) {
    asm volatile("ldmatrix.sync.aligned.m8n8.x4.shared.b16 {%0,%1,%2,%3}, [%4];"
        : "=r"(r[0]), "=r"(r[1]), "=r"(r[2]), "=r"(r[3]) : "r"(addr));
}
__device__ __forceinline__ void ldsm4t(uint32_t* r, uint32_t addr) {
    asm volatile("ldmatrix.sync.aligned.m8n8.x4.trans.shared.b16 {%0,%1,%2,%3}, [%4];"
        : "=r"(r[0]), "=r"(r[1]), "=r"(r[2]), "=r"(r[3]) : "r"(addr));
}
__device__ __forceinline__ void mma_f16(float* d, const uint32_t* a, const uint32_t* b) {
    asm volatile("mma.sync.aligned.m16n8k16.row.col.f32.f16.f16.f32 "
        "{%0,%1,%2,%3}, {%4,%5,%6,%7}, {%8,%9}, {%0,%1,%2,%3};"
        : "+f"(d[0]), "+f"(d[1]), "+f"(d[2]), "+f"(d[3])
        : "r"(a[0]), "r"(a[1]), "r"(a[2]), "r"(a[3]), "r"(b[0]), "r"(b[1]));
}
__device__ __forceinline__ uint32_t sw128(uint32_t off) {
    return off ^ ((off >> 3) & 0x70);
}
__device__ __forceinline__ uint32_t pack2h(float a, float b) {
    __half2 h = __floats2half2_rn(a, b);
    return *(uint32_t*)&h;
}

// ---------------- lengths from key_padding_mask (dtype-robust) ----------------
__global__ void lengths_kernel(const unsigned char* mraw) {
    __shared__ int s_cnt[BATCH];
    __shared__ int s_isbool;
    int tid = threadIdx.x;
    if (tid < BATCH) s_cnt[tid] = 0;
    if (tid == 0) s_isbool = (mraw[1] | mraw[2] | mraw[3]) ? 1 : 0;
    __syncthreads();
    for (int b = 0; b < BATCH; b++) {
        int c = 0;
        if (s_isbool) {
            const unsigned char* p = mraw + (size_t)b * SEQ;
            for (int t = tid; t < SEQ; t += blockDim.x) c += p[t] ? 1 : 0;
        } else {
            const int* p = (const int*)mraw + (size_t)b * SEQ;
            for (int t = tid; t < SEQ; t += blockDim.x) c += p[t] ? 1 : 0;
        }
        atomicAdd(&s_cnt[b], c);
    }
    __syncthreads();
    if (tid < BATCH) g_len[tid] = s_cnt[tid];
}

// ---------------- weight transpose -> fp16: W[K,N] -> T[N,K] ----------------
__global__ void __launch_bounds__(256) wsplit_h_kernel(
    const float* __restrict__ W, __half* __restrict__ T,
    int K, int N, int rowOff, int ldt)
{
    __shared__ float t[32][33];
    int n0 = blockIdx.x * 32, k0 = blockIdx.y * 32;
    int tx = threadIdx.x & 31, ty = threadIdx.x >> 5;
    #pragma unroll
    for (int i = 0; i < 32; i += 8)
        t[ty + i][tx] = W[(size_t)(k0 + ty + i) * N + n0 + tx];
    __syncthreads();
    #pragma unroll
    for (int i = 0; i < 32; i += 8)
        T[(size_t)(rowOff + n0 + ty + i) * ldt + k0 + tx] = __float2half(t[tx][ty + i]);
}

// ---------------- LayerNorm -> masked, fp16 output (dead rows: zero fast path) ----------------
__global__ void __launch_bounds__(256) ln_half_kernel(
    const float* __restrict__ x, const float* __restrict__ w,
    const float* __restrict__ bia, __half* __restrict__ y)
{
    int row = blockIdx.x;
    int b = row >> 11, t = row & (SEQ - 1);
    if (t >= g_len[b]) {   // dead row -> zeros (uniform branch per block)
        uint2 z = make_uint2(0, 0);
        for (int i = threadIdx.x * 4; i < EMB; i += 1024)
            *(uint2*)&y[(size_t)row * EMB + i] = z;
        return;
    }
    const float* xr = x + (size_t)row * EMB;
    float s = 0.f, sq = 0.f;
    for (int i = threadIdx.x; i < EMB; i += 256) { float v = xr[i]; s += v; sq += v * v; }
    #pragma unroll
    for (int o = 16; o; o >>= 1) {
        s  += __shfl_xor_sync(~0u, s,  o);
        sq += __shfl_xor_sync(~0u, sq, o);
    }
    __shared__ float red[16];
    __shared__ float s_mu, s_rstd;
    int wid = threadIdx.x >> 5, lid = threadIdx.x & 31;
    if (lid == 0) { red[wid] = s; red[8 + wid] = sq; }
    __syncthreads();
    if (threadIdx.x == 0) {
        float S = 0.f, SQ = 0.f;
        for (int i = 0; i < 8; i++) { S += red[i]; SQ += red[8 + i]; }
        float mu = S * (1.f / EMB);
        float var = SQ * (1.f / EMB) - mu * mu;
        s_mu = mu; s_rstd = rsqrtf(var + 1e-5f);
    }
    __syncthreads();
    float mu = s_mu, rstd = s_rstd;
    for (int i = threadIdx.x; i < EMB; i += 256)
        y[(size_t)row * EMB + i] = __float2half((xr[i] - mu) * rstd * w[i] + bia[i]);
}

// ---------------- single-term fp16 GEMM, K-chunk 64, 3-stage, 2 CTAs/SM ----------------
// C[M,N] = A @ B^T. 128x128 tile, 8 warps (2x4). M rows are sequence rows:
// blocks fully beyond g_len[batch] zero-fill and exit (dead-row elision).
#define GEMM_SMEM (3 * 32768)

__global__ void __launch_bounds__(256, 2) gemm_fp16(
    const __half* __restrict__ A, const __half* __restrict__ B,
    const float* __restrict__ Res, const float* __restrict__ Bias,
    float* __restrict__ Cf, __half* __restrict__ Ch,
    int K, int ldc, int doRelu, int doMask)
{
    extern __shared__ char smem[];
    uint32_t sb = smem_u32(smem);
    int tid = threadIdx.x;
    int lane = tid & 31, wid = tid >> 5;
    int wm = (wid >> 2) * 64;
    int wn = (wid & 3) * 32;
    int m0 = blockIdx.y * 128, n0 = blockIdx.x * 128;

    // ---- dead-row elision: whole 128-row block beyond this batch's length ----
    {
        int bb = m0 >> 11;
        if ((m0 & (SEQ - 1)) >= g_len[bb]) {
            #pragma unroll
            for (int it = 0; it < 16; it++) {
                int idx = tid + it * 256;
                int rr = idx >> 5, cc = (idx & 31) * 4;
                size_t o = (size_t)(m0 + rr) * ldc + n0 + cc;
                if (Ch) *(uint2*)&Ch[o] = make_uint2(0, 0);
                else    *(float4*)&Cf[o] = make_float4(0.f, 0.f, 0.f, 0.f);
            }
            return;
        }
    }

    int nc = K >> 6;   // chunks of 64 columns (128B rows of half)

    auto load_chunk = [&](uint32_t st, int kc) {
        #pragma unroll
        for (int i = 0; i < 8; i++) {
            int g = tid + i * 256;          // 0..2047
            int tile = g >> 10;             // 0 = A, 1 = B
            int rem = g & 1023;
            int r = rem >> 3, u = rem & 7;
            uint32_t sw = sw128(r * 128 + u * 16);
            int col = kc + u * 8;
            const __half* src = (tile == 0) ? A + (size_t)(m0 + r) * K + col
                                            : B + (size_t)(n0 + r) * K + col;
            cp_async16(st + tile * 16384 + sw, src);
        }
        CP_COMMIT();
    };

    int grp = lane >> 3, lrow = lane & 7;
    int a_r = lrow + ((grp & 1) ? 8 : 0);
    int a_c = grp >> 1;
    int b_r = lrow + ((grp >> 1) ? 8 : 0);
    int b_c = grp & 1;

    float d[4][4][4];
    #pragma unroll
    for (int i = 0; i < 4; i++)
        #pragma unroll
        for (int j = 0; j < 4; j++)
            #pragma unroll
            for (int q = 0; q < 4; q++) d[i][j][q] = 0.f;

    load_chunk(sb, 0);
    load_chunk(sb + 32768, 64);
    CP_WAIT1();
    __syncthreads();

    for (int c = 0; c < nc; c++) {
        uint32_t st = sb + (c % 3) * 32768;
        if (c + 2 < nc) load_chunk(sb + ((c + 2) % 3) * 32768, (c + 2) * 64);

        #pragma unroll
        for (int ks = 0; ks < 4; ks++) {
            uint32_t ah[4][4];
            #pragma unroll
            for (int mt = 0; mt < 4; mt++) {
                uint32_t rb = (wm + mt * 16 + a_r) * 128;
                ldsm4(ah[mt], st + sw128(rb + (2 * ks + a_c) * 16));
            }
            #pragma unroll
            for (int np = 0; np < 2; np++) {
                uint32_t rb = (wn + np * 16 + b_r) * 128;
                uint32_t th[4];
                ldsm4(th, st + 16384 + sw128(rb + (2 * ks + b_c) * 16));
                #pragma unroll
                for (int mt = 0; mt < 4; mt++) {
                    mma_f16(d[mt][np * 2],     ah[mt], &th[0]);
                    mma_f16(d[mt][np * 2 + 1], ah[mt], &th[2]);
                }
            }
        }
        if (c + 2 < nc) CP_WAIT1(); else CP_WAIT0();
        __syncthreads();
    }

    // ---- epilogue: stage f32 accum through smem ----
    float* eb = (float*)smem;    // [128][132]
    int fr = lane >> 2, fc = (lane & 3) * 2;
    #pragma unroll
    for (int mt = 0; mt < 4; mt++)
        #pragma unroll
        for (int nt = 0; nt < 4; nt++) {
            int rr = wm + mt * 16 + fr;
            int cc = wn + nt * 8 + fc;
            *(float2*)&eb[rr * 132 + cc]       = make_float2(d[mt][nt][0], d[mt][nt][1]);
            *(float2*)&eb[(rr + 8) * 132 + cc] = make_float2(d[mt][nt][2], d[mt][nt][3]);
        }
    __syncthreads();

    #pragma unroll
    for (int it = 0; it < 16; it++) {
        int idx = tid + it * 256;
        int rr = idx >> 5;
        int cc = (idx & 31) * 4;
        int m = m0 + rr, n = n0 + cc;
        float4 v = *(float4*)&eb[rr * 132 + cc];
        if (Bias) {
            v.x += Bias[n]; v.y += Bias[n + 1]; v.z += Bias[n + 2]; v.w += Bias[n + 3];
        }
        if (Res) {
            float4 rv = *(const float4*)&Res[(size_t)m * ldc + n];
            v.x += rv.x; v.y += rv.y; v.z += rv.z; v.w += rv.w;
        }
        if (doRelu) {
            v.x = fmaxf(v.x, 0.f); v.y = fmaxf(v.y, 0.f);
            v.z = fmaxf(v.z, 0.f); v.w = fmaxf(v.w, 0.f);
        }
        if (doMask) {
            int bb = m >> 11, t = m & (SEQ - 1);
            float mk = (t < g_len[bb]) ? 1.f : 0.f;
            v.x *= mk; v.y *= mk; v.z *= mk; v.w *= mk;
        }
        if (Ch) {
            uint32_t p0 = pack2h(v.x, v.y), p1 = pack2h(v.z, v.w);
            *(uint2*)&Ch[(size_t)m * ldc + n] = make_uint2(p0, p1);
        } else {
            *(float4*)&Cf[(size_t)m * ldc + n] = v;
        }
    }
}

// ---------------- Flash attention, single-term fp16 mma (64q, 4 warps) ----------------
#define ATTN_SMEM (3 * 8192)

__global__ void __launch_bounds__(128) attn_f16_kernel(
    const __half* __restrict__ QKV, __half* __restrict__ O)
{
    extern __shared__ char smem[];
    uint32_t sb = smem_u32(smem);
    const uint32_t sQ = sb, sK = sb + 8192, sV = sb + 16384;
    int tid = threadIdx.x, lane = tid & 31, wid = tid >> 5;
    int b = blockIdx.z, h = blockIdx.y, qt = blockIdx.x;
    int q0 = qt * 64;
    int len = g_len[b];
    size_t rowbase = (size_t)b * SEQ;
    int cq = h * HS, ck = EMB + h * HS, cv = 2 * EMB + h * HS;

    // ---- dead q-tile elision: all rows beyond len -> zero output ----
    if (q0 >= len) {
        #pragma unroll
        for (int i = 0; i < 4; i++) {
            int idx = tid + i * 128;           // 0..511 -> 64 rows x 8 half2-cols? 64x64 half = 512 uint4
            int r = idx >> 3, c = (idx & 7) * 8;
            *(uint4*)&O[(rowbase + q0 + r) * EMB + h * HS + c] = make_uint4(0, 0, 0, 0);
        }
        return;
    }

    // load Q tile (64 rows x 128B)
    #pragma unroll
    for (int i = 0; i < 4; i++) {
        int idx = tid + i * 128;
        int r = idx >> 3, c16 = idx & 7;
        uint32_t sw = sw128(r * 128 + c16 * 16);
        cp_async16(sQ + sw, QKV + (rowbase + q0 + r) * QKVW + cq + c16 * 8);
    }
    CP_COMMIT();

    float Oacc[8][4];
    #pragma unroll
    for (int j = 0; j < 8; j++)
        #pragma unroll
        for (int q = 0; q < 4; q++) Oacc[j][q] = 0.f;
    float mrow0 = -1e30f, mrow1 = -1e30f, lrow0 = 0.f, lrow1 = 0.f;

    const float scale = 0.03125f;  // 1024^-0.5
    int lenTiles = (len + 63) >> 6;
    int nT = min(qt + 1, lenTiles);

    int l15 = lane & 15, lh = lane >> 4;
    int grp = lane >> 3, lrow = lane & 7;
    int b_r = lrow + ((grp >> 1) ? 8 : 0);   // B-operand lane addressing
    int b_c = grp & 1;
    int wq = wid * 16;
    int r0 = q0 + wq + (lane >> 2);
    int dlo = (lane & 3) * 2;

    for (int kt = 0; kt < nT; kt++) {
        int s0 = kt * 64;
        __syncthreads();
        #pragma unroll
        for (int i = 0; i < 4; i++) {
            int idx = tid + i * 128;
            int r = idx >> 3, c16 = idx & 7;
            uint32_t sw = sw128(r * 128 + c16 * 16);
            size_t gg = (rowbase + s0 + r) * QKVW + c16 * 8;
            cp_async16(sK + sw, QKV + gg + ck);
            cp_async16(sV + sw, QKV + gg + cv);
        }
        CP_COMMIT();
        CP_WAIT0();
        __syncthreads();

        // ---- S = Q K^T ----
        float sacc[8][4];
        #pragma unroll
        for (int j = 0; j < 8; j++)
            #pragma unroll
            for (int q = 0; q < 4; q++) sacc[j][q] = 0.f;

        #pragma unroll
        for (int ks = 0; ks < 4; ks++) {
            uint32_t qf[4];
            ldsm4(qf, sQ + sw128((wq + l15) * 128 + (ks * 2 + lh) * 16));
            #pragma unroll
            for (int np = 0; np < 4; np++) {
                uint32_t kf[4];
                ldsm4(kf, sK + sw128((np * 16 + b_r) * 128 + (ks * 2 + b_c) * 16));
                mma_f16(sacc[np * 2],     qf, &kf[0]);
                mma_f16(sacc[np * 2 + 1], qf, &kf[2]);
            }
        }

        // ---- scale + mask + row max ----
        float rmax0 = -1e30f, rmax1 = -1e30f;
        #pragma unroll
        for (int j = 0; j < 8; j++) {
            int kj = s0 + j * 8 + dlo;
            #pragma unroll
            for (int q = 0; q < 4; q++) {
                int col = kj + (q & 1);
                int row = r0 + (q >> 1) * 8;
                float v = sacc[j][q] * scale;
                if (col > row || col >= len) v = -1e30f;
                sacc[j][q] = v;
            }
            rmax0 = fmaxf(rmax0, fmaxf(sacc[j][0], sacc[j][1]));
            rmax1 = fmaxf(rmax1, fmaxf(sacc[j][2], sacc[j][3]));
        }
        rmax0 = fmaxf(rmax0, __shfl_xor_sync(~0u, rmax0, 1));
        rmax0 = fmaxf(rmax0, __shfl_xor_sync(~0u, rmax0, 2));
        rmax1 = fmaxf(rmax1, __shfl_xor_sync(~0u, rmax1, 1));
        rmax1 = fmaxf(rmax1, __shfl_xor_sync(~0u, rmax1, 2));

        float mnew0 = fmaxf(mrow0, rmax0), mnew1 = fmaxf(mrow1, rmax1);
        float corr0 = __expf(mrow0 - mnew0), corr1 = __expf(mrow1 - mnew1);
        mrow0 = mnew0; mrow1 = mnew1;

        // ---- P = exp(S - m), row sums ----
        float rsum0 = 0.f, rsum1 = 0.f;
        #pragma unroll
        for (int j = 0; j < 8; j++) {
            sacc[j][0] = __expf(sacc[j][0] - mnew0);
            sacc[j][1] = __expf(sacc[j][1] - mnew0);
            sacc[j][2] = __expf(sacc[j][2] - mnew1);
            sacc[j][3] = __expf(sacc[j][3] - mnew1);
            rsum0 += sacc[j][0] + sacc[j][1];
            rsum1 += sacc[j][2] + sacc[j][3];
        }
        rsum0 += __shfl_xor_sync(~0u, rsum0, 1);
        rsum0 += __shfl_xor_sync(~0u, rsum0, 2);
        rsum1 += __shfl_xor_sync(~0u, rsum1, 1);
        rsum1 += __shfl_xor_sync(~0u, rsum1, 2);
        lrow0 = lrow0 * corr0 + rsum0;
        lrow1 = lrow1 * corr1 + rsum1;

        // ---- rescale O ----
        #pragma unroll
        for (int j = 0; j < 8; j++) {
            Oacc[j][0] *= corr0; Oacc[j][1] *= corr0;
            Oacc[j][2] *= corr1; Oacc[j][3] *= corr1;
        }

        // ---- O += P @ V ----
        #pragma unroll
        for (int ks = 0; ks < 4; ks++) {
            int j0 = 2 * ks, j1 = j0 + 1;
            uint32_t pf[4];
            pf[0] = pack2h(sacc[j0][0], sacc[j0][1]);
            pf[1] = pack2h(sacc[j0][2], sacc[j0][3]);
            pf[2] = pack2h(sacc[j1][0], sacc[j1][1]);
            pf[3] = pack2h(sacc[j1][2], sacc[j1][3]);
            #pragma unroll
            for (int dg = 0; dg < 4; dg++) {
                uint32_t vf[4];
                ldsm4t(vf, sV + sw128((ks * 16 + l15) * 128 + (dg * 2 + lh) * 16));
                mma_f16(Oacc[dg * 2],     pf, &vf[0]);
                mma_f16(Oacc[dg * 2 + 1], pf, &vf[2]);
            }
        }
    }

    // ---- final: O /= l, write fp16 ----
    float inv0 = 1.f / lrow0, inv1 = 1.f / lrow1;
    size_t row0 = rowbase + r0, row1 = row0 + 8;
    #pragma unroll
    for (int j = 0; j < 8; j++) {
        int dc = h * HS + j * 8 + dlo;
        *(uint32_t*)&O[row0 * EMB + dc] = pack2h(Oacc[j][0] * inv0, Oacc[j][1] * inv0);
        *(uint32_t*)&O[row1 * EMB + dc] = pack2h(Oacc[j][2] * inv1, Oacc[j][3] * inv1);
    }
}

// ---------------- launch ----------------
extern "C" void kernel_launch(void* const* d_in, const int* in_sizes, int n_in,
                              void* d_out, int out_size)
{
    const float* x      = (const float*)d_in[0];
    const unsigned char* mask = (const unsigned char*)d_in[1];
    const float* wq     = (const float*)d_in[2];
    const float* wk     = (const float*)d_in[3];
    const float* wv     = (const float*)d_in[4];
    const float* proj_w = (const float*)d_in[5];
    const float* proj_b = (const float*)d_in[6];
    const float* ff_w1  = (const float*)d_in[7];
    const float* ff_b1  = (const float*)d_in[8];
    const float* ff_w2  = (const float*)d_in[9];
    const float* ff_b2  = (const float*)d_in[10];
    const float* ln1w   = (const float*)d_in[11];
    const float* ln1b   = (const float*)d_in[12];
    const float* ln2w   = (const float*)d_in[13];
    const float* ln2b   = (const float*)d_in[14];
    float* out = (float*)d_out;

    __half *hbuf, *qkv, *ffh, *wqkv, *wproj, *wff1, *wff2;
    float *x1;
    cudaGetSymbolAddress((void**)&hbuf, g_h);
    cudaGetSymbolAddress((void**)&qkv, g_qkv);
    cudaGetSymbolAddress((void**)&ffh, g_ffh);
    cudaGetSymbolAddress((void**)&wqkv, g_wqkv);
    cudaGetSymbolAddress((void**)&wproj, g_wproj);
    cudaGetSymbolAddress((void**)&wff1, g_wff1);
    cudaGetSymbolAddress((void**)&wff2, g_wff2);
    cudaGetSymbolAddress((void**)&x1, g_x1);

    cudaFuncSetAttribute(gemm_fp16, cudaFuncAttributeMaxDynamicSharedMemorySize, GEMM_SMEM);
    cudaFuncSetAttribute(attn_f16_kernel, cudaFuncAttributeMaxDynamicSharedMemorySize, ATTN_SMEM);

    lengths_kernel<<<1, 256>>>(mask);

    // weight prep (transpose + fp16)
    wsplit_h_kernel<<<dim3(EMB/32, EMB/32), 256>>>(wq, wqkv, EMB, EMB, 0,     EMB);
    wsplit_h_kernel<<<dim3(EMB/32, EMB/32), 256>>>(wk, wqkv, EMB, EMB, EMB,   EMB);
    wsplit_h_kernel<<<dim3(EMB/32, EMB/32), 256>>>(wv, wqkv, EMB, EMB, 2*EMB, EMB);
    wsplit_h_kernel<<<dim3(EMB/32, EMB/32), 256>>>(proj_w, wproj, EMB, EMB, 0, EMB);
    wsplit_h_kernel<<<dim3(DFF/32, EMB/32), 256>>>(ff_w1, wff1, EMB, DFF, 0, EMB);
    wsplit_h_kernel<<<dim3(EMB/32, DFF/32), 256>>>(ff_w2, wff2, DFF, EMB, 0, DFF);

    // h = LN1(x)*m (fp16)
    ln_half_kernel<<<MROWS, 256>>>(x, ln1w, ln1b, hbuf);

    // qkv = h @ Wqkv^T -> fp16  [8192 x 3072]
    gemm_fp16<<<dim3(QKVW/128, MROWS/128), 256, GEMM_SMEM>>>(
        hbuf, wqkv, nullptr, nullptr, nullptr, qkv, EMB, QKVW, 0, 0);

    // attention (fp16 flash) -> hbuf (reuse)
    attn_f16_kernel<<<dim3(SEQ/64, NH, BATCH), 128, ATTN_SMEM>>>(qkv, hbuf);

    // x1 = x + attn @ proj_w + proj_b
    gemm_fp16<<<dim3(EMB/128, MROWS/128), 256, GEMM_SMEM>>>(
        hbuf, wproj, x, proj_b, x1, nullptr, EMB, EMB, 0, 0);

    // h2 = LN2(x1)*m (fp16) -> hbuf
    ln_half_kernel<<<MROWS, 256>>>(x1, ln2w, ln2b, hbuf);

    // ff = relu(h2 @ ff_w1 + b1) -> fp16
    gemm_fp16<<<dim3(DFF/128, MROWS/128), 256, GEMM_SMEM>>>(
        hbuf, wff1, nullptr, ff_b1, nullptr, ffh, EMB, DFF, 1, 0);

    // out = (x1 + ff @ ff_w2 + b2) * m
    gemm_fp16<<<dim3(EMB/128, MROWS/128), 256, GEMM_SMEM>>>(
        ffh, wff2, x1, ff_b2, out, nullptr, DFF, EMB, 0, 1);
}